// round 9
// baseline (speedup 1.0000x reference)
#include <cuda_runtime.h>
#include <cuda_fp16.h>
#include <stdint.h>

#define BATCH 4
#define NSEQ  4096
#define DDIM  1024
#define EDIM  1024

typedef __half f16;

// ---------------- scratch (device globals; no allocations allowed) -------------
__device__ f16 g_xh[(size_t)BATCH*NSEQ*DDIM], g_xl[(size_t)BATCH*NSEQ*DDIM];
__device__ f16 g_yh[(size_t)BATCH*NSEQ*DDIM], g_yl[(size_t)BATCH*NSEQ*DDIM];
__device__ f16 g_wqh[(size_t)EDIM*DDIM], g_wql[(size_t)EDIM*DDIM];
__device__ f16 g_wkh[(size_t)EDIM*DDIM], g_wkl[(size_t)EDIM*DDIM];
__device__ f16 g_wvh[(size_t)EDIM*DDIM], g_wvl[(size_t)EDIM*DDIM];
__device__ f16 g_woh[(size_t)DDIM*EDIM], g_wol[(size_t)DDIM*EDIM];
__device__ f16 g_qh[(size_t)BATCH*NSEQ*EDIM], g_ql[(size_t)BATCH*NSEQ*EDIM];
__device__ f16 g_kh[(size_t)BATCH*NSEQ*EDIM], g_kl[(size_t)BATCH*NSEQ*EDIM];
__device__ f16 g_vh[(size_t)BATCH*NSEQ*EDIM], g_vl[(size_t)BATCH*NSEQ*EDIM];
__device__ f16 g_vth[(size_t)BATCH*EDIM*NSEQ], g_vtl[(size_t)BATCH*EDIM*NSEQ];
__device__ f16 g_ph[(size_t)BATCH*NSEQ*NSEQ], g_pl[(size_t)BATCH*NSEQ*NSEQ];
__device__ f16 g_ch[(size_t)BATCH*NSEQ*EDIM], g_cl[(size_t)BATCH*NSEQ*EDIM];
__device__ float g_spart[(size_t)BATCH*NSEQ*32];
__device__ float g_rinv[(size_t)BATCH*NSEQ];

// ---------------- helpers ----------------
__device__ __forceinline__ uint32_t smem_u32(const void* p) {
    uint32_t a;
    asm("{ .reg .u64 t; cvta.to.shared.u64 t, %1; cvt.u32.u64 %0, t; }" : "=r"(a) : "l"(p));
    return a;
}
__device__ __forceinline__ void cpa16(uint32_t dst, const void* src) {
    asm volatile("cp.async.cg.shared.global [%0], [%1], 16;" :: "r"(dst), "l"(src));
}

// f16 x f16 -> f32 accumulate (dominant hh term)
#define MMA_F32ACC(c, a, b) \
    asm volatile("mma.sync.aligned.m16n8k16.row.col.f32.f16.f16.f32 " \
                 "{%0,%1,%2,%3},{%4,%5,%6,%7},{%8,%9},{%0,%1,%2,%3};\n" \
                 : "+f"(c[0]), "+f"(c[1]), "+f"(c[2]), "+f"(c[3]) \
                 : "r"(a[0]), "r"(a[1]), "r"(a[2]), "r"(a[3]), "r"(b[0]), "r"(b[1]))

// f16 x f16 -> f16 accumulate (correction terms)
#define MMA_F16ACC(c, a, b) \
    asm volatile("mma.sync.aligned.m16n8k16.row.col.f16.f16.f16.f16 " \
                 "{%0,%1},{%2,%3,%4,%5},{%6,%7},{%0,%1};\n" \
                 : "+r"(c[0]), "+r"(c[1]) \
                 : "r"(a[0]), "r"(a[1]), "r"(a[2]), "r"(a[3]), "r"(b[0]), "r"(b[1]))

#define LDSM4(r, a) \
    asm volatile("ldmatrix.sync.aligned.m8n8.x4.shared.b16 {%0,%1,%2,%3}, [%4];\n" \
                 : "=r"((r)[0]), "=r"((r)[1]), "=r"((r)[2]), "=r"((r)[3]) : "r"(a))
#define LDSM2(r, a) \
    asm volatile("ldmatrix.sync.aligned.m8n8.x2.shared.b16 {%0,%1}, [%2];\n" \
                 : "=r"((r)[0]), "=r"((r)[1]) : "r"(a))

// ---------------- fp32 -> f16 hi/lo split (batched over z) ----------------
__device__ __forceinline__ void split_one(const float4* src, f16* hi, f16* lo, int i)
{
    float4 v = src[i];
    float vs[4] = {v.x, v.y, v.z, v.w};
    f16 h[4], l[4];
#pragma unroll
    for (int j = 0; j < 4; j++) {
        h[j] = __float2half_rn(vs[j]);
        l[j] = __float2half_rn(vs[j] - __half2float(h[j]));
    }
    __half2 h01; h01.x = h[0]; h01.y = h[1];
    __half2 h23; h23.x = h[2]; h23.y = h[3];
    __half2 l01; l01.x = l[0]; l01.y = l[1];
    __half2 l23; l23.x = l[2]; l23.y = l[3];
    reinterpret_cast<__half2*>(hi)[2*i]   = h01;
    reinterpret_cast<__half2*>(hi)[2*i+1] = h23;
    reinterpret_cast<__half2*>(lo)[2*i]   = l01;
    reinterpret_cast<__half2*>(lo)[2*i+1] = l23;
}

__global__ void split_xy(const float4* __restrict__ x, f16* xh, f16* xl,
                         const float4* __restrict__ y, f16* yh, f16* yl, int n4)
{
    int i = blockIdx.x * blockDim.x + threadIdx.x;
    if (i >= n4) return;
    if (blockIdx.z == 0) split_one(x, xh, xl, i);
    else                 split_one(y, yh, yl, i);
}

__global__ void split_w(const float4* __restrict__ wq, f16* wqh, f16* wql,
                        const float4* __restrict__ wk, f16* wkh, f16* wkl,
                        const float4* __restrict__ wv, f16* wvh, f16* wvl,
                        const float4* __restrict__ wo, f16* woh, f16* wol, int n4)
{
    int i = blockIdx.x * blockDim.x + threadIdx.x;
    if (i >= n4) return;
    switch (blockIdx.z) {
        case 0: split_one(wq, wqh, wql, i); break;
        case 1: split_one(wk, wkh, wkl, i); break;
        case 2: split_one(wv, wvh, wvl, i); break;
        default: split_one(wo, woh, wol, i); break;
    }
}

// ---------------- f16 transpose per batch: in [NSEQ, EDIM] -> out [EDIM, NSEQ] ---
__global__ __launch_bounds__(256)
void transpose_k(const f16* __restrict__ in, f16* __restrict__ out,
                 const f16* __restrict__ in2, f16* __restrict__ out2)
{
    __shared__ f16 t[64][72];
    const int z = blockIdx.z & 3;
    const f16* src = (blockIdx.z < 4) ? in : in2;
    f16* dst       = (blockIdx.z < 4) ? out : out2;
    src += (size_t)z * NSEQ * EDIM;
    dst += (size_t)z * EDIM * NSEQ;
    const int x0 = blockIdx.x * 64;
    const int y0 = blockIdx.y * 64;
    const int tid = threadIdx.x;
    const int r = tid >> 3, c = (tid & 7) * 8;
#pragma unroll
    for (int i = 0; i < 2; i++) {
        uint4 v = *(const uint4*)(src + (size_t)(y0 + r + 32*i) * EDIM + x0 + c);
        *(uint4*)&t[r + 32*i][c] = v;
    }
    __syncthreads();
#pragma unroll
    for (int i = 0; i < 2; i++) {
        int orow = r + 32*i;
        f16 tmp[8];
#pragma unroll
        for (int j = 0; j < 8; j++) tmp[j] = t[c + j][orow];
        *(uint4*)(dst + (size_t)(x0 + orow) * NSEQ + y0 + c) = *(uint4*)tmp;
    }
}

// ---------------- rowsum partials -> 1/sum ----------------
__global__ void rowsum_inv(const float* __restrict__ spart, float* __restrict__ rinv, int nrows)
{
    int r = blockIdx.x * 256 + threadIdx.x;
    if (r >= nrows) return;
    float s = 0.0f;
#pragma unroll
    for (int j = 0; j < 32; j++) s += spart[(size_t)r * 32 + j];
    rinv[r] = 1.0f / s;
}

// ---------------- HMMA split-f16 GEMM: C = (Ah+Al)(Bh+Bl)^T -------------------
// hh term -> f32 acc; cross terms (ah*bl + al*bh) -> shared f16 acc.
// CTA tile 128x128, K_TILE=32, 3-stage cp.async, 8 warps (64x32 each).
// OUT_MODE: 1 split hi/lo f16; 2 fp32+bias; 3 exp(acc/32) split + row partials;
//           4 acc*rinv[row] split.

#define NSTAGE   3
#define MAT_B    (128 * 80)
#define STAGE_B  (4 * MAT_B)                 // Ah, Al, Bh, Bl
#define SMEM_B   (NSTAGE * STAGE_B)          // 122880

template<int OUT_MODE>
__global__ __launch_bounds__(256, 1)
void gemm_hmma(const f16* __restrict__ Ah, const f16* __restrict__ Al,
               const f16* __restrict__ Bh, const f16* __restrict__ Bl,
               float* __restrict__ outF, f16* __restrict__ outHi, f16* __restrict__ outLo,
               const float* __restrict__ bias,
               float* __restrict__ spart, const float* __restrict__ rowscale,
               int M, int N, int K, long long sA, long long sB, long long sC)
{
    extern __shared__ __align__(16) char dsm[];
    __shared__ float part[128][4];
    const uint32_t sb = smem_u32(dsm);

    const int z = blockIdx.z;
    Ah += (size_t)z * sA;  Al += (size_t)z * sA;
    Bh += (size_t)z * sB;  Bl += (size_t)z * sB;

    const int tid = threadIdx.x;
    const int lane = tid & 31;
    const int warp = tid >> 5;
    const int m0 = blockIdx.y * 128;
    const int n0 = blockIdx.x * 128;

    const int wm0 = (warp & 1) * 64;          // 2 warps along M
    const int wn0 = (warp >> 1) * 32;         // 4 warps along N
    const int arow = lane & 15;
    const int acol = (lane >> 4) * 8;
    const int brow = lane & 7;
    const int bcol = ((lane >> 3) & 1) * 8;

    const int nk = K >> 5;

    const int ar0 = tid >> 2,          ac0 = (tid & 3);
    const int ar1 = (tid + 256) >> 2,  ac1 = ((tid + 256) & 3);

    auto load_stage = [&](int kt, int stg) {
        const uint32_t base = sb + stg * STAGE_B;
        const int kk = kt << 5;
        {
            uint32_t d = base + ar0 * 80 + ac0 * 16;
            const size_t ga = (size_t)(m0 + ar0) * K + kk + ac0 * 8;
            const size_t gb = (size_t)(n0 + ar0) * K + kk + ac0 * 8;
            cpa16(d,             Ah + ga);
            cpa16(d + MAT_B,     Al + ga);
            cpa16(d + 2*MAT_B,   Bh + gb);
            cpa16(d + 3*MAT_B,   Bl + gb);
        }
        {
            uint32_t d = base + ar1 * 80 + ac1 * 16;
            const size_t ga = (size_t)(m0 + ar1) * K + kk + ac1 * 8;
            const size_t gb = (size_t)(n0 + ar1) * K + kk + ac1 * 8;
            cpa16(d,             Ah + ga);
            cpa16(d + MAT_B,     Al + ga);
            cpa16(d + 2*MAT_B,   Bh + gb);
            cpa16(d + 3*MAT_B,   Bl + gb);
        }
        asm volatile("cp.async.commit_group;" ::: "memory");
    };

    float   hh[4][4][4];
    uint32_t cx[4][4][2];
#pragma unroll
    for (int t = 0; t < 4; t++)
#pragma unroll
        for (int u = 0; u < 4; u++) {
#pragma unroll
            for (int e = 0; e < 4; e++) hh[t][u][e] = 0.0f;
            cx[t][u][0] = 0u; cx[t][u][1] = 0u;
        }

    load_stage(0, 0);
    load_stage(1, 1);

    for (int kt = 0; kt < nk; kt++) {
        asm volatile("cp.async.wait_group 1;" ::: "memory");
        __syncthreads();

        if (kt + 2 < nk) load_stage(kt + 2, (kt + 2) % NSTAGE);
        else             asm volatile("cp.async.commit_group;" ::: "memory");

        const uint32_t base = sb + (kt % NSTAGE) * STAGE_B;

#pragma unroll
        for (int ks = 0; ks < 2; ks++) {
            const int kbyte = ks * 32;
            uint32_t ah[4][4], al[4][4], bh[4][2], bl[4][2];
#pragma unroll
            for (int t = 0; t < 4; t++) {
                uint32_t ad = base + (uint32_t)(wm0 + t*16 + arow) * 80 + kbyte + acol * 2;
                LDSM4(ah[t], ad);
                LDSM4(al[t], ad + MAT_B);
            }
#pragma unroll
            for (int u = 0; u < 4; u++) {
                uint32_t bd = base + 2*MAT_B + (uint32_t)(wn0 + u*8 + brow) * 80 + kbyte + bcol * 2;
                LDSM2(bh[u], bd);
                LDSM2(bl[u], bd + MAT_B);
            }
            // hh (f32 acc), then cross terms (f16 acc) — term-outermost for independence
#pragma unroll
            for (int t = 0; t < 4; t++)
#pragma unroll
                for (int u = 0; u < 4; u++) MMA_F32ACC(hh[t][u], ah[t], bh[u]);
#pragma unroll
            for (int t = 0; t < 4; t++)
#pragma unroll
                for (int u = 0; u < 4; u++) MMA_F16ACC(cx[t][u], ah[t], bl[u]);
#pragma unroll
            for (int t = 0; t < 4; t++)
#pragma unroll
                for (int u = 0; u < 4; u++) MMA_F16ACC(cx[t][u], al[t], bh[u]);
        }
    }

    // ---- epilogue: combine hh + cross, then mode-specific output ----
    const size_t cbase = (size_t)z * sC;
#pragma unroll
    for (int t = 0; t < 4; t++) {
        const int gm = m0 + wm0 + t * 16 + (lane >> 2);
        float rs0 = 0.0f, rs1 = 0.0f;
        float rv0 = 1.0f, rv1 = 1.0f;
        if (OUT_MODE == 4) {
            rv0 = rowscale[(size_t)z * M + gm];
            rv1 = rowscale[(size_t)z * M + gm + 8];
        }
#pragma unroll
        for (int u = 0; u < 4; u++) {
            const int gn = n0 + wn0 + u * 8 + (lane & 3) * 2;
            float2 c01 = __half22float2(*(__half2*)&cx[t][u][0]);
            float2 c23 = __half22float2(*(__half2*)&cx[t][u][1]);
            float v00 = hh[t][u][0] + c01.x, v01 = hh[t][u][1] + c01.y;
            float v10 = hh[t][u][2] + c23.x, v11 = hh[t][u][3] + c23.y;
            if (OUT_MODE == 2) {
                float b0 = bias[gn], b1 = bias[gn + 1];
                v00 += b0; v01 += b1; v10 += b0; v11 += b1;
            }
            if (OUT_MODE == 3) {
                v00 = __expf(v00 * 0.03125f);
                v01 = __expf(v01 * 0.03125f);
                v10 = __expf(v10 * 0.03125f);
                v11 = __expf(v11 * 0.03125f);
                rs0 += v00 + v01;
                rs1 += v10 + v11;
            }
            if (OUT_MODE == 4) {
                v00 *= rv0; v01 *= rv0; v10 *= rv1; v11 *= rv1;
            }
            if (OUT_MODE == 2) {
                *(float2*)(outF + cbase + (size_t)gm * N + gn) = make_float2(v00, v01);
                *(float2*)(outF + cbase + (size_t)(gm + 8) * N + gn) = make_float2(v10, v11);
            } else {
                f16 h00 = __float2half_rn(v00), h01 = __float2half_rn(v01);
                f16 h10 = __float2half_rn(v10), h11 = __float2half_rn(v11);
                __half2 hp0; hp0.x = h00; hp0.y = h01;
                __half2 hp1; hp1.x = h10; hp1.y = h11;
                __half2 lp0; lp0.x = __float2half_rn(v00 - __half2float(h00));
                             lp0.y = __float2half_rn(v01 - __half2float(h01));
                __half2 lp1; lp1.x = __float2half_rn(v10 - __half2float(h10));
                             lp1.y = __float2half_rn(v11 - __half2float(h11));
                *(__half2*)(outHi + cbase + (size_t)gm * N + gn) = hp0;
                *(__half2*)(outHi + cbase + (size_t)(gm + 8) * N + gn) = hp1;
                *(__half2*)(outLo + cbase + (size_t)gm * N + gn) = lp0;
                *(__half2*)(outLo + cbase + (size_t)(gm + 8) * N + gn) = lp1;
            }
        }
        if (OUT_MODE == 3) {
            rs0 += __shfl_xor_sync(0xffffffffu, rs0, 1);
            rs0 += __shfl_xor_sync(0xffffffffu, rs0, 2);
            rs1 += __shfl_xor_sync(0xffffffffu, rs1, 1);
            rs1 += __shfl_xor_sync(0xffffffffu, rs1, 2);
            if ((lane & 3) == 0) {
                part[wm0 + t * 16 + (lane >> 2)][warp >> 1] = rs0;
                part[wm0 + t * 16 + (lane >> 2) + 8][warp >> 1] = rs1;
            }
        }
    }
    if (OUT_MODE == 3) {
        __syncthreads();
        if (tid < 128) {
            float s = part[tid][0] + part[tid][1] + part[tid][2] + part[tid][3];
            spart[((size_t)z * M + m0 + tid) * 32 + blockIdx.x] = s;
        }
    }
}

// ---------------- host ----------------
extern "C" void kernel_launch(void* const* d_in, const int* in_sizes, int n_in,
                              void* d_out, int out_size)
{
    const float* x  = (const float*)d_in[0];
    const float* y  = (const float*)d_in[1];
    const float* Wq = (const float*)d_in[2];
    const float* Wk = (const float*)d_in[3];
    const float* Wv = (const float*)d_in[4];
    const float* Wo = (const float*)d_in[5];
    const float* bo = (const float*)d_in[6];
    float* out = (float*)d_out;

#define GET(sym, var) void* var; cudaGetSymbolAddress(&var, sym)
    GET(g_xh, xh); GET(g_xl, xl); GET(g_yh, yh); GET(g_yl, yl);
    GET(g_wqh, wqh); GET(g_wql, wql); GET(g_wkh, wkh); GET(g_wkl, wkl);
    GET(g_wvh, wvh); GET(g_wvl, wvl); GET(g_woh, woh); GET(g_wol, wol);
    GET(g_qh, qh); GET(g_ql, ql); GET(g_kh, kh); GET(g_kl, kl);
    GET(g_vh, vh); GET(g_vl, vl); GET(g_vth, vth); GET(g_vtl, vtl);
    GET(g_ph, ph); GET(g_pl, pl); GET(g_ch, ch); GET(g_cl, cl);
    GET(g_spart, spart); GET(g_rinv, rinv);
#undef GET

    cudaFuncSetAttribute(gemm_hmma<1>, cudaFuncAttributeMaxDynamicSharedMemorySize, SMEM_B);
    cudaFuncSetAttribute(gemm_hmma<2>, cudaFuncAttributeMaxDynamicSharedMemorySize, SMEM_B);
    cudaFuncSetAttribute(gemm_hmma<3>, cudaFuncAttributeMaxDynamicSharedMemorySize, SMEM_B);
    cudaFuncSetAttribute(gemm_hmma<4>, cudaFuncAttributeMaxDynamicSharedMemorySize, SMEM_B);

    const int MBN = BATCH * NSEQ;            // 16384

    // launches 0-1: splits (batched)
    {
        int n4 = BATCH * NSEQ * DDIM / 4;
        dim3 g1(n4 / 256, 1, 2);
        split_xy<<<g1, 256>>>((const float4*)x, (f16*)xh, (f16*)xl,
                              (const float4*)y, (f16*)yh, (f16*)yl, n4);
        int w4 = EDIM * DDIM / 4;
        dim3 g2(w4 / 256, 1, 4);
        split_w<<<g2, 256>>>((const float4*)Wq, (f16*)wqh, (f16*)wql,
                             (const float4*)Wk, (f16*)wkh, (f16*)wkl,
                             (const float4*)Wv, (f16*)wvh, (f16*)wvl,
                             (const float4*)Wo, (f16*)woh, (f16*)wol, w4);
    }

    // launches 2-4: projections (M=16384, N=1024, K=1024)
    {
        dim3 grid(EDIM / 128, MBN / 128, 1);
        gemm_hmma<1><<<grid, 256, SMEM_B>>>((f16*)yh, (f16*)yl, (f16*)wqh, (f16*)wql,
                                            nullptr, (f16*)qh, (f16*)ql, nullptr,
                                            nullptr, nullptr, MBN, EDIM, DDIM, 0, 0, 0);
        gemm_hmma<1><<<grid, 256, SMEM_B>>>((f16*)xh, (f16*)xl, (f16*)wkh, (f16*)wkl,
                                            nullptr, (f16*)kh, (f16*)kl, nullptr,
                                            nullptr, nullptr, MBN, EDIM, DDIM, 0, 0, 0);
        gemm_hmma<1><<<grid, 256, SMEM_B>>>((f16*)xh, (f16*)xl, (f16*)wvh, (f16*)wvl,
                                            nullptr, (f16*)vh, (f16*)vl, nullptr,
                                            nullptr, nullptr, MBN, EDIM, DDIM, 0, 0, 0);
    }

    // launch 5: scores+exp (ncu -s 5 -c 1 profiles this)
    {
        dim3 grid(NSEQ / 128, NSEQ / 128, BATCH);
        gemm_hmma<3><<<grid, 256, SMEM_B>>>((f16*)qh, (f16*)ql, (f16*)kh, (f16*)kl,
                                            nullptr, (f16*)ph, (f16*)pl, nullptr,
                                            (float*)spart, nullptr,
                                            NSEQ, NSEQ, EDIM,
                                            (long long)NSEQ * EDIM, (long long)NSEQ * EDIM,
                                            (long long)NSEQ * NSEQ);
    }

    // rinv = 1/rowsum from partials
    rowsum_inv<<<MBN / 256, 256>>>((const float*)spart, (float*)rinv, MBN);

    // transpose V (hi+lo in one launch)
    {
        dim3 grid(EDIM / 64, NSEQ / 64, 2 * BATCH);
        transpose_k<<<grid, 256>>>((f16*)vh, (f16*)vth, (f16*)vl, (f16*)vtl);
    }

    // ctx: C[b] = rinv ⊙ (E[b] @ V[b]) (M=4096, N=1024, K=4096)
    {
        dim3 grid(EDIM / 128, NSEQ / 128, BATCH);
        gemm_hmma<4><<<grid, 256, SMEM_B>>>((f16*)ph, (f16*)pl, (f16*)vth, (f16*)vtl,
                                            nullptr, (f16*)ch, (f16*)cl, nullptr,
                                            nullptr, (const float*)rinv,
                                            NSEQ, EDIM, NSEQ,
                                            (long long)NSEQ * NSEQ, (long long)EDIM * NSEQ,
                                            (long long)NSEQ * EDIM);
    }

    // out = ctx @ Wo^T + bo (M=16384, N=1024, K=1024)
    {
        dim3 grid(DDIM / 128, MBN / 128, 1);
        gemm_hmma<2><<<grid, 256, SMEM_B>>>((f16*)ch, (f16*)cl, (f16*)woh, (f16*)wol,
                                            out, nullptr, nullptr, bo,
                                            nullptr, nullptr, MBN, DDIM, EDIM, 0, 0, 0);
    }

    (void)in_sizes; (void)n_in; (void)out_size;
}

// round 10
// speedup vs baseline: 1.3313x; 1.3313x over previous
#include <cuda_runtime.h>
#include <cuda_fp16.h>
#include <stdint.h>

#define BATCH 4
#define NSEQ  4096
#define DDIM  1024
#define EDIM  1024

typedef __half f16;

// ---------------- scratch (device globals; no allocations allowed) -------------
__device__ f16 g_xh[(size_t)BATCH*NSEQ*DDIM], g_xl[(size_t)BATCH*NSEQ*DDIM];
__device__ f16 g_yh[(size_t)BATCH*NSEQ*DDIM], g_yl[(size_t)BATCH*NSEQ*DDIM];
__device__ f16 g_wqh[(size_t)EDIM*DDIM], g_wql[(size_t)EDIM*DDIM];
__device__ f16 g_wkh[(size_t)EDIM*DDIM], g_wkl[(size_t)EDIM*DDIM];
__device__ f16 g_wvh[(size_t)EDIM*DDIM], g_wvl[(size_t)EDIM*DDIM];
__device__ f16 g_woh[(size_t)DDIM*EDIM], g_wol[(size_t)DDIM*EDIM];
__device__ f16 g_qh[(size_t)BATCH*NSEQ*EDIM], g_ql[(size_t)BATCH*NSEQ*EDIM];
__device__ f16 g_kh[(size_t)BATCH*NSEQ*EDIM], g_kl[(size_t)BATCH*NSEQ*EDIM];
__device__ f16 g_vh[(size_t)BATCH*NSEQ*EDIM], g_vl[(size_t)BATCH*NSEQ*EDIM];
__device__ f16 g_vth[(size_t)BATCH*EDIM*NSEQ];
__device__ f16 g_ph[(size_t)BATCH*NSEQ*NSEQ], g_pl[(size_t)BATCH*NSEQ*NSEQ];
__device__ f16 g_ch[(size_t)BATCH*NSEQ*EDIM], g_cl[(size_t)BATCH*NSEQ*EDIM];
__device__ float g_spart[(size_t)BATCH*NSEQ*32];
__device__ float g_rinv[(size_t)BATCH*NSEQ];

// ---------------- helpers ----------------
__device__ __forceinline__ uint32_t smem_u32(const void* p) {
    uint32_t a;
    asm("{ .reg .u64 t; cvta.to.shared.u64 t, %1; cvt.u32.u64 %0, t; }" : "=r"(a) : "l"(p));
    return a;
}
__device__ __forceinline__ void cpa16(uint32_t dst, const void* src) {
    asm volatile("cp.async.cg.shared.global [%0], [%1], 16;" :: "r"(dst), "l"(src));
}

#define MMA_F32ACC(c, a, b) \
    asm volatile("mma.sync.aligned.m16n8k16.row.col.f32.f16.f16.f32 " \
                 "{%0,%1,%2,%3},{%4,%5,%6,%7},{%8,%9},{%0,%1,%2,%3};\n" \
                 : "+f"(c[0]), "+f"(c[1]), "+f"(c[2]), "+f"(c[3]) \
                 : "r"(a[0]), "r"(a[1]), "r"(a[2]), "r"(a[3]), "r"(b[0]), "r"(b[1]))

#define MMA_F16ACC(c, a, b) \
    asm volatile("mma.sync.aligned.m16n8k16.row.col.f16.f16.f16.f16 " \
                 "{%0,%1},{%2,%3,%4,%5},{%6,%7},{%0,%1};\n" \
                 : "+r"(c[0]), "+r"(c[1]) \
                 : "r"(a[0]), "r"(a[1]), "r"(a[2]), "r"(a[3]), "r"(b[0]), "r"(b[1]))

#define LDSM4(r, a) \
    asm volatile("ldmatrix.sync.aligned.m8n8.x4.shared.b16 {%0,%1,%2,%3}, [%4];\n" \
                 : "=r"((r)[0]), "=r"((r)[1]), "=r"((r)[2]), "=r"((r)[3]) : "r"(a))
#define LDSM2(r, a) \
    asm volatile("ldmatrix.sync.aligned.m8n8.x2.shared.b16 {%0,%1}, [%2];\n" \
                 : "=r"((r)[0]), "=r"((r)[1]) : "r"(a))

// ---------------- fp32 -> f16 hi/lo split (batched over z) ----------------
__device__ __forceinline__ void split_one(const float4* src, f16* hi, f16* lo, int i)
{
    float4 v = src[i];
    float vs[4] = {v.x, v.y, v.z, v.w};
    f16 h[4], l[4];
#pragma unroll
    for (int j = 0; j < 4; j++) {
        h[j] = __float2half_rn(vs[j]);
        l[j] = __float2half_rn(vs[j] - __half2float(h[j]));
    }
    __half2 h01; h01.x = h[0]; h01.y = h[1];
    __half2 h23; h23.x = h[2]; h23.y = h[3];
    __half2 l01; l01.x = l[0]; l01.y = l[1];
    __half2 l23; l23.x = l[2]; l23.y = l[3];
    reinterpret_cast<__half2*>(hi)[2*i]   = h01;
    reinterpret_cast<__half2*>(hi)[2*i+1] = h23;
    reinterpret_cast<__half2*>(lo)[2*i]   = l01;
    reinterpret_cast<__half2*>(lo)[2*i+1] = l23;
}

__global__ void split_xy(const float4* __restrict__ x, f16* xh, f16* xl,
                         const float4* __restrict__ y, f16* yh, f16* yl, int n4)
{
    int i = blockIdx.x * blockDim.x + threadIdx.x;
    if (i >= n4) return;
    if (blockIdx.z == 0) split_one(x, xh, xl, i);
    else                 split_one(y, yh, yl, i);
}

__global__ void split_w(const float4* __restrict__ wq, f16* wqh, f16* wql,
                        const float4* __restrict__ wk, f16* wkh, f16* wkl,
                        const float4* __restrict__ wv, f16* wvh, f16* wvl,
                        const float4* __restrict__ wo, f16* woh, f16* wol, int n4)
{
    int i = blockIdx.x * blockDim.x + threadIdx.x;
    if (i >= n4) return;
    switch (blockIdx.z) {
        case 0: split_one(wq, wqh, wql, i); break;
        case 1: split_one(wk, wkh, wkl, i); break;
        case 2: split_one(wv, wvh, wvl, i); break;
        default: split_one(wo, woh, wol, i); break;
    }
}

// ---------------- f16 transpose per batch: in [NSEQ, EDIM] -> out [EDIM, NSEQ] ---
__global__ __launch_bounds__(256)
void transpose_k(const f16* __restrict__ in, f16* __restrict__ out)
{
    __shared__ f16 t[64][72];
    const int z = blockIdx.z;
    in  += (size_t)z * NSEQ * EDIM;
    out += (size_t)z * EDIM * NSEQ;
    const int x0 = blockIdx.x * 64;
    const int y0 = blockIdx.y * 64;
    const int tid = threadIdx.x;
    const int r = tid >> 3, c = (tid & 7) * 8;
#pragma unroll
    for (int i = 0; i < 2; i++) {
        uint4 v = *(const uint4*)(in + (size_t)(y0 + r + 32*i) * EDIM + x0 + c);
        *(uint4*)&t[r + 32*i][c] = v;
    }
    __syncthreads();
#pragma unroll
    for (int i = 0; i < 2; i++) {
        int orow = r + 32*i;
        f16 tmp[8];
#pragma unroll
        for (int j = 0; j < 8; j++) tmp[j] = t[c + j][orow];
        *(uint4*)(out + (size_t)(x0 + orow) * NSEQ + y0 + c) = *(uint4*)tmp;
    }
}

// ---------------- rowsum partials -> 1/sum ----------------
__global__ void rowsum_inv(const float* __restrict__ spart, float* __restrict__ rinv, int nrows)
{
    int r = blockIdx.x * 256 + threadIdx.x;
    if (r >= nrows) return;
    float s = 0.0f;
#pragma unroll
    for (int j = 0; j < 32; j++) s += spart[(size_t)r * 32 + j];
    rinv[r] = 1.0f / s;
}

// ---------------- HMMA split-f16 GEMM (TERMS-configurable) --------------------
// C = A·B^T with A=(Ah[+Al]), B=(Bh[+Bl]) per TERMS:
//   TERMS=1: Ah·Bh                 (single precision)
//   TERMS=2: Ah·Bh + Al·Bh         (A split, B single)
//   TERMS=3: Ah·Bh + Ah·Bl + Al·Bh (both split)
// hh term -> f32 acc; correction terms -> shared f16 acc.
// CTA 128x128, K_TILE=32, 3-stage cp.async, 8 warps (64x32).
// OUT_MODE: 1 split hi/lo f16; 2 fp32+bias; 3 exp(acc/32) split + row partials;
//           4 acc*rinv[row] split.

#define NSTAGE   3
#define MAT_B    (128 * 80)
#define STAGE_B  (4 * MAT_B)
#define SMEM_B   (NSTAGE * STAGE_B)

template<int OUT_MODE, int TERMS>
__global__ __launch_bounds__(256, 1)
void gemm_hmma(const f16* __restrict__ Ah, const f16* __restrict__ Al,
               const f16* __restrict__ Bh, const f16* __restrict__ Bl,
               float* __restrict__ outF, f16* __restrict__ outHi, f16* __restrict__ outLo,
               const float* __restrict__ bias,
               float* __restrict__ spart, const float* __restrict__ rowscale,
               int M, int N, int K, long long sA, long long sB, long long sC)
{
    extern __shared__ __align__(16) char dsm[];
    __shared__ float part[128][4];
    const uint32_t sb = smem_u32(dsm);

    const int z = blockIdx.z;
    Ah += (size_t)z * sA;
    if (TERMS >= 2) Al += (size_t)z * sA;
    Bh += (size_t)z * sB;
    if (TERMS >= 3) Bl += (size_t)z * sB;

    const int tid = threadIdx.x;
    const int lane = tid & 31;
    const int warp = tid >> 5;
    const int m0 = blockIdx.y * 128;
    const int n0 = blockIdx.x * 128;

    const int wm0 = (warp & 1) * 64;
    const int wn0 = (warp >> 1) * 32;
    const int arow = lane & 15;
    const int acol = (lane >> 4) * 8;
    const int brow = lane & 7;
    const int bcol = ((lane >> 3) & 1) * 8;

    const int nk = K >> 5;

    const int ar0 = tid >> 2,          ac0 = (tid & 3);
    const int ar1 = (tid + 256) >> 2,  ac1 = ((tid + 256) & 3);

    auto load_stage = [&](int kt, int stg) {
        const uint32_t base = sb + stg * STAGE_B;
        const int kk = kt << 5;
        {
            uint32_t d = base + ar0 * 80 + ac0 * 16;
            const size_t ga = (size_t)(m0 + ar0) * K + kk + ac0 * 8;
            const size_t gb = (size_t)(n0 + ar0) * K + kk + ac0 * 8;
            cpa16(d,           Ah + ga);
            if (TERMS >= 2) cpa16(d + MAT_B, Al + ga);
            cpa16(d + 2*MAT_B, Bh + gb);
            if (TERMS >= 3) cpa16(d + 3*MAT_B, Bl + gb);
        }
        {
            uint32_t d = base + ar1 * 80 + ac1 * 16;
            const size_t ga = (size_t)(m0 + ar1) * K + kk + ac1 * 8;
            const size_t gb = (size_t)(n0 + ar1) * K + kk + ac1 * 8;
            cpa16(d,           Ah + ga);
            if (TERMS >= 2) cpa16(d + MAT_B, Al + ga);
            cpa16(d + 2*MAT_B, Bh + gb);
            if (TERMS >= 3) cpa16(d + 3*MAT_B, Bl + gb);
        }
        asm volatile("cp.async.commit_group;" ::: "memory");
    };

    float    hh[4][4][4];
    uint32_t cx[4][4][2];
#pragma unroll
    for (int t = 0; t < 4; t++)
#pragma unroll
        for (int u = 0; u < 4; u++) {
#pragma unroll
            for (int e = 0; e < 4; e++) hh[t][u][e] = 0.0f;
            cx[t][u][0] = 0u; cx[t][u][1] = 0u;
        }

    load_stage(0, 0);
    load_stage(1, 1);

    for (int kt = 0; kt < nk; kt++) {
        asm volatile("cp.async.wait_group 1;" ::: "memory");
        __syncthreads();

        if (kt + 2 < nk) load_stage(kt + 2, (kt + 2) % NSTAGE);
        else             asm volatile("cp.async.commit_group;" ::: "memory");

        const uint32_t base = sb + (kt % NSTAGE) * STAGE_B;

#pragma unroll
        for (int ks = 0; ks < 2; ks++) {
            const int kbyte = ks * 32;
            uint32_t ah[4][4], al[4][4], bh[4][2], bl[4][2];
#pragma unroll
            for (int t = 0; t < 4; t++) {
                uint32_t ad = base + (uint32_t)(wm0 + t*16 + arow) * 80 + kbyte + acol * 2;
                LDSM4(ah[t], ad);
                if (TERMS >= 2) LDSM4(al[t], ad + MAT_B);
            }
#pragma unroll
            for (int u = 0; u < 4; u++) {
                uint32_t bd = base + 2*MAT_B + (uint32_t)(wn0 + u*8 + brow) * 80 + kbyte + bcol * 2;
                LDSM2(bh[u], bd);
                if (TERMS >= 3) LDSM2(bl[u], bd + MAT_B);
            }
#pragma unroll
            for (int t = 0; t < 4; t++)
#pragma unroll
                for (int u = 0; u < 4; u++) MMA_F32ACC(hh[t][u], ah[t], bh[u]);
            if (TERMS >= 3) {
#pragma unroll
                for (int t = 0; t < 4; t++)
#pragma unroll
                    for (int u = 0; u < 4; u++) MMA_F16ACC(cx[t][u], ah[t], bl[u]);
            }
            if (TERMS >= 2) {
#pragma unroll
                for (int t = 0; t < 4; t++)
#pragma unroll
                    for (int u = 0; u < 4; u++) MMA_F16ACC(cx[t][u], al[t], bh[u]);
            }
        }
    }

    // ---- epilogue ----
    const size_t cbase = (size_t)z * sC;
#pragma unroll
    for (int t = 0; t < 4; t++) {
        const int gm = m0 + wm0 + t * 16 + (lane >> 2);
        float rs0 = 0.0f, rs1 = 0.0f;
        float rv0 = 1.0f, rv1 = 1.0f;
        if (OUT_MODE == 4) {
            rv0 = rowscale[(size_t)z * M + gm];
            rv1 = rowscale[(size_t)z * M + gm + 8];
        }
#pragma unroll
        for (int u = 0; u < 4; u++) {
            const int gn = n0 + wn0 + u * 8 + (lane & 3) * 2;
            float v00 = hh[t][u][0], v01 = hh[t][u][1];
            float v10 = hh[t][u][2], v11 = hh[t][u][3];
            if (TERMS >= 2) {
                float2 c01 = __half22float2(*(__half2*)&cx[t][u][0]);
                float2 c23 = __half22float2(*(__half2*)&cx[t][u][1]);
                v00 += c01.x; v01 += c01.y; v10 += c23.x; v11 += c23.y;
            }
            if (OUT_MODE == 2) {
                float b0 = bias[gn], b1 = bias[gn + 1];
                v00 += b0; v01 += b1; v10 += b0; v11 += b1;
            }
            if (OUT_MODE == 3) {
                v00 = __expf(v00 * 0.03125f);
                v01 = __expf(v01 * 0.03125f);
                v10 = __expf(v10 * 0.03125f);
                v11 = __expf(v11 * 0.03125f);
                rs0 += v00 + v01;
                rs1 += v10 + v11;
            }
            if (OUT_MODE == 4) {
                v00 *= rv0; v01 *= rv0; v10 *= rv1; v11 *= rv1;
            }
            if (OUT_MODE == 2) {
                *(float2*)(outF + cbase + (size_t)gm * N + gn) = make_float2(v00, v01);
                *(float2*)(outF + cbase + (size_t)(gm + 8) * N + gn) = make_float2(v10, v11);
            } else {
                f16 h00 = __float2half_rn(v00), h01 = __float2half_rn(v01);
                f16 h10 = __float2half_rn(v10), h11 = __float2half_rn(v11);
                __half2 hp0; hp0.x = h00; hp0.y = h01;
                __half2 hp1; hp1.x = h10; hp1.y = h11;
                __half2 lp0; lp0.x = __float2half_rn(v00 - __half2float(h00));
                             lp0.y = __float2half_rn(v01 - __half2float(h01));
                __half2 lp1; lp1.x = __float2half_rn(v10 - __half2float(h10));
                             lp1.y = __float2half_rn(v11 - __half2float(h11));
                *(__half2*)(outHi + cbase + (size_t)gm * N + gn) = hp0;
                *(__half2*)(outHi + cbase + (size_t)(gm + 8) * N + gn) = hp1;
                *(__half2*)(outLo + cbase + (size_t)gm * N + gn) = lp0;
                *(__half2*)(outLo + cbase + (size_t)(gm + 8) * N + gn) = lp1;
            }
        }
        if (OUT_MODE == 3) {
            rs0 += __shfl_xor_sync(0xffffffffu, rs0, 1);
            rs0 += __shfl_xor_sync(0xffffffffu, rs0, 2);
            rs1 += __shfl_xor_sync(0xffffffffu, rs1, 1);
            rs1 += __shfl_xor_sync(0xffffffffu, rs1, 2);
            if ((lane & 3) == 0) {
                part[wm0 + t * 16 + (lane >> 2)][warp >> 1] = rs0;
                part[wm0 + t * 16 + (lane >> 2) + 8][warp >> 1] = rs1;
            }
        }
    }
    if (OUT_MODE == 3) {
        __syncthreads();
        if (tid < 128) {
            float s = part[tid][0] + part[tid][1] + part[tid][2] + part[tid][3];
            spart[((size_t)z * M + m0 + tid) * 32 + blockIdx.x] = s;
        }
    }
}

// ---------------- host ----------------
extern "C" void kernel_launch(void* const* d_in, const int* in_sizes, int n_in,
                              void* d_out, int out_size)
{
    const float* x  = (const float*)d_in[0];
    const float* y  = (const float*)d_in[1];
    const float* Wq = (const float*)d_in[2];
    const float* Wk = (const float*)d_in[3];
    const float* Wv = (const float*)d_in[4];
    const float* Wo = (const float*)d_in[5];
    const float* bo = (const float*)d_in[6];
    float* out = (float*)d_out;

#define GET(sym, var) void* var; cudaGetSymbolAddress(&var, sym)
    GET(g_xh, xh); GET(g_xl, xl); GET(g_yh, yh); GET(g_yl, yl);
    GET(g_wqh, wqh); GET(g_wql, wql); GET(g_wkh, wkh); GET(g_wkl, wkl);
    GET(g_wvh, wvh); GET(g_wvl, wvl); GET(g_woh, woh); GET(g_wol, wol);
    GET(g_qh, qh); GET(g_ql, ql); GET(g_kh, kh); GET(g_kl, kl);
    GET(g_vh, vh); GET(g_vl, vl); GET(g_vth, vth);
    GET(g_ph, ph); GET(g_pl, pl); GET(g_ch, ch); GET(g_cl, cl);
    GET(g_spart, spart); GET(g_rinv, rinv);
#undef GET

    cudaFuncSetAttribute((void*)gemm_hmma<1,3>, cudaFuncAttributeMaxDynamicSharedMemorySize, SMEM_B);
    cudaFuncSetAttribute((void*)gemm_hmma<2,3>, cudaFuncAttributeMaxDynamicSharedMemorySize, SMEM_B);
    cudaFuncSetAttribute((void*)gemm_hmma<3,1>, cudaFuncAttributeMaxDynamicSharedMemorySize, SMEM_B);
    cudaFuncSetAttribute((void*)gemm_hmma<4,2>, cudaFuncAttributeMaxDynamicSharedMemorySize, SMEM_B);

    const int MBN = BATCH * NSEQ;            // 16384

    // splits (batched)
    {
        int n4 = BATCH * NSEQ * DDIM / 4;
        dim3 g1(n4 / 256, 1, 2);
        split_xy<<<g1, 256>>>((const float4*)x, (f16*)xh, (f16*)xl,
                              (const float4*)y, (f16*)yh, (f16*)yl, n4);
        int w4 = EDIM * DDIM / 4;
        dim3 g2(w4 / 256, 1, 4);
        split_w<<<g2, 256>>>((const float4*)Wq, (f16*)wqh, (f16*)wql,
                             (const float4*)Wk, (f16*)wkh, (f16*)wkl,
                             (const float4*)Wv, (f16*)wvh, (f16*)wvl,
                             (const float4*)Wo, (f16*)woh, (f16*)wol, w4);
    }

    // projections (3-term): q,k,v
    {
        dim3 grid(EDIM / 128, MBN / 128, 1);
        gemm_hmma<1,3><<<grid, 256, SMEM_B>>>((f16*)yh, (f16*)yl, (f16*)wqh, (f16*)wql,
                                              nullptr, (f16*)qh, (f16*)ql, nullptr,
                                              nullptr, nullptr, MBN, EDIM, DDIM, 0, 0, 0);
        gemm_hmma<1,3><<<grid, 256, SMEM_B>>>((f16*)xh, (f16*)xl, (f16*)wkh, (f16*)wkl,
                                              nullptr, (f16*)kh, (f16*)kl, nullptr,
                                              nullptr, nullptr, MBN, EDIM, DDIM, 0, 0, 0);
        gemm_hmma<1,3><<<grid, 256, SMEM_B>>>((f16*)xh, (f16*)xl, (f16*)wvh, (f16*)wvl,
                                              nullptr, (f16*)vh, (f16*)vl, nullptr,
                                              nullptr, nullptr, MBN, EDIM, DDIM, 0, 0, 0);
    }

    // scores+exp (single-term: qh·kh), split E + row partials
    {
        dim3 grid(NSEQ / 128, NSEQ / 128, BATCH);
        gemm_hmma<3,1><<<grid, 256, SMEM_B>>>((f16*)qh, nullptr, (f16*)kh, nullptr,
                                              nullptr, (f16*)ph, (f16*)pl, nullptr,
                                              (float*)spart, nullptr,
                                              NSEQ, NSEQ, EDIM,
                                              (long long)NSEQ * EDIM, (long long)NSEQ * EDIM,
                                              (long long)NSEQ * NSEQ);
    }

    // rinv = 1/rowsum from partials
    rowsum_inv<<<MBN / 256, 256>>>((const float*)spart, (float*)rinv, MBN);

    // transpose V-hi only
    {
        dim3 grid(EDIM / 64, NSEQ / 64, BATCH);
        transpose_k<<<grid, 256>>>((f16*)vh, (f16*)vth);
    }

    // ctx (2-term: (Eh+El)·Vh), scaled by rinv
    {
        dim3 grid(EDIM / 128, NSEQ / 128, BATCH);
        gemm_hmma<4,2><<<grid, 256, SMEM_B>>>((f16*)ph, (f16*)pl, (f16*)vth, nullptr,
                                              nullptr, (f16*)ch, (f16*)cl, nullptr,
                                              nullptr, (const float*)rinv,
                                              NSEQ, EDIM, NSEQ,
                                              (long long)NSEQ * NSEQ, (long long)EDIM * NSEQ,
                                              (long long)NSEQ * EDIM);
    }

    // out = ctx @ Wo^T + bo (3-term)
    {
        dim3 grid(DDIM / 128, MBN / 128, 1);
        gemm_hmma<2,3><<<grid, 256, SMEM_B>>>((f16*)ch, (f16*)cl, (f16*)woh, (f16*)wol,
                                              out, nullptr, nullptr, bo,
                                              nullptr, nullptr, MBN, DDIM, EDIM, 0, 0, 0);
    }

    (void)in_sizes; (void)n_in; (void)out_size;
}

// round 11
// speedup vs baseline: 1.7129x; 1.2867x over previous
#include <cuda_runtime.h>
#include <cuda_fp16.h>
#include <stdint.h>

#define BATCH 4
#define NSEQ  4096
#define DDIM  1024
#define EDIM  1024

typedef __half f16;

// ---------------- scratch (device globals; no allocations allowed) -------------
__device__ f16 g_xh[(size_t)BATCH*NSEQ*DDIM], g_xl[(size_t)BATCH*NSEQ*DDIM];
__device__ f16 g_yh[(size_t)BATCH*NSEQ*DDIM], g_yl[(size_t)BATCH*NSEQ*DDIM];
__device__ f16 g_wqh[(size_t)EDIM*DDIM];
__device__ f16 g_wkh[(size_t)EDIM*DDIM];
__device__ f16 g_wvh[(size_t)EDIM*DDIM];
__device__ f16 g_woh[(size_t)DDIM*EDIM], g_wol[(size_t)DDIM*EDIM];
__device__ f16 g_qh[(size_t)BATCH*NSEQ*EDIM];
__device__ f16 g_kh[(size_t)BATCH*NSEQ*EDIM];
__device__ f16 g_vh[(size_t)BATCH*NSEQ*EDIM];
__device__ f16 g_vth[(size_t)BATCH*EDIM*NSEQ];
__device__ f16 g_ph[(size_t)BATCH*NSEQ*NSEQ];
__device__ f16 g_ch[(size_t)BATCH*NSEQ*EDIM], g_cl[(size_t)BATCH*NSEQ*EDIM];
__device__ float g_spart[(size_t)BATCH*NSEQ*32];
__device__ float g_rinv[(size_t)BATCH*NSEQ];

// ---------------- helpers ----------------
__device__ __forceinline__ uint32_t smem_u32(const void* p) {
    uint32_t a;
    asm("{ .reg .u64 t; cvta.to.shared.u64 t, %1; cvt.u32.u64 %0, t; }" : "=r"(a) : "l"(p));
    return a;
}
__device__ __forceinline__ void cpa16(uint32_t dst, const void* src) {
    asm volatile("cp.async.cg.shared.global [%0], [%1], 16;" :: "r"(dst), "l"(src));
}

#define MMA_F32ACC(c, a, b) \
    asm volatile("mma.sync.aligned.m16n8k16.row.col.f32.f16.f16.f32 " \
                 "{%0,%1,%2,%3},{%4,%5,%6,%7},{%8,%9},{%0,%1,%2,%3};\n" \
                 : "+f"(c[0]), "+f"(c[1]), "+f"(c[2]), "+f"(c[3]) \
                 : "r"(a[0]), "r"(a[1]), "r"(a[2]), "r"(a[3]), "r"(b[0]), "r"(b[1]))

#define MMA_F16ACC(c, a, b) \
    asm volatile("mma.sync.aligned.m16n8k16.row.col.f16.f16.f16.f16 " \
                 "{%0,%1},{%2,%3,%4,%5},{%6,%7},{%0,%1};\n" \
                 : "+r"(c[0]), "+r"(c[1]) \
                 : "r"(a[0]), "r"(a[1]), "r"(a[2]), "r"(a[3]), "r"(b[0]), "r"(b[1]))

#define LDSM4(r, a) \
    asm volatile("ldmatrix.sync.aligned.m8n8.x4.shared.b16 {%0,%1,%2,%3}, [%4];\n" \
                 : "=r"((r)[0]), "=r"((r)[1]), "=r"((r)[2]), "=r"((r)[3]) : "r"(a))
#define LDSM2(r, a) \
    asm volatile("ldmatrix.sync.aligned.m8n8.x2.shared.b16 {%0,%1}, [%2];\n" \
                 : "=r"((r)[0]), "=r"((r)[1]) : "r"(a))

// ---------------- fp32 -> f16 hi/lo split (batched over z) ----------------
__device__ __forceinline__ void split_one(const float4* src, f16* hi, f16* lo, int i)
{
    float4 v = src[i];
    float vs[4] = {v.x, v.y, v.z, v.w};
    f16 h[4], l[4];
#pragma unroll
    for (int j = 0; j < 4; j++) {
        h[j] = __float2half_rn(vs[j]);
        l[j] = __float2half_rn(vs[j] - __half2float(h[j]));
    }
    __half2 h01; h01.x = h[0]; h01.y = h[1];
    __half2 h23; h23.x = h[2]; h23.y = h[3];
    reinterpret_cast<__half2*>(hi)[2*i]   = h01;
    reinterpret_cast<__half2*>(hi)[2*i+1] = h23;
    if (lo) {
        __half2 l01; l01.x = l[0]; l01.y = l[1];
        __half2 l23; l23.x = l[2]; l23.y = l[3];
        reinterpret_cast<__half2*>(lo)[2*i]   = l01;
        reinterpret_cast<__half2*>(lo)[2*i+1] = l23;
    }
}

__global__ void split_xy(const float4* __restrict__ x, f16* xh, f16* xl,
                         const float4* __restrict__ y, f16* yh, f16* yl, int n4)
{
    int i = blockIdx.x * blockDim.x + threadIdx.x;
    if (i >= n4) return;
    if (blockIdx.z == 0) split_one(x, xh, xl, i);
    else                 split_one(y, yh, yl, i);
}

__global__ void split_w(const float4* __restrict__ wq, f16* wqh,
                        const float4* __restrict__ wk, f16* wkh,
                        const float4* __restrict__ wv, f16* wvh,
                        const float4* __restrict__ wo, f16* woh, f16* wol, int n4)
{
    int i = blockIdx.x * blockDim.x + threadIdx.x;
    if (i >= n4) return;
    switch (blockIdx.z) {
        case 0: split_one(wq, wqh, nullptr, i); break;
        case 1: split_one(wk, wkh, nullptr, i); break;
        case 2: split_one(wv, wvh, nullptr, i); break;
        default: split_one(wo, woh, wol, i); break;
    }
}

// ---------------- f16 transpose per batch: in [NSEQ, EDIM] -> out [EDIM, NSEQ] ---
__global__ __launch_bounds__(256)
void transpose_k(const f16* __restrict__ in, f16* __restrict__ out)
{
    __shared__ f16 t[64][72];
    const int z = blockIdx.z;
    in  += (size_t)z * NSEQ * EDIM;
    out += (size_t)z * EDIM * NSEQ;
    const int x0 = blockIdx.x * 64;
    const int y0 = blockIdx.y * 64;
    const int tid = threadIdx.x;
    const int r = tid >> 3, c = (tid & 7) * 8;
#pragma unroll
    for (int i = 0; i < 2; i++) {
        uint4 v = *(const uint4*)(in + (size_t)(y0 + r + 32*i) * EDIM + x0 + c);
        *(uint4*)&t[r + 32*i][c] = v;
    }
    __syncthreads();
#pragma unroll
    for (int i = 0; i < 2; i++) {
        int orow = r + 32*i;
        f16 tmp[8];
#pragma unroll
        for (int j = 0; j < 8; j++) tmp[j] = t[c + j][orow];
        *(uint4*)(out + (size_t)(x0 + orow) * NSEQ + y0 + c) = *(uint4*)tmp;
    }
}

// ---------------- rowsum partials -> 1/sum ----------------
__global__ void rowsum_inv(const float* __restrict__ spart, float* __restrict__ rinv, int nrows)
{
    int r = blockIdx.x * 256 + threadIdx.x;
    if (r >= nrows) return;
    float s = 0.0f;
#pragma unroll
    for (int j = 0; j < 32; j++) s += spart[(size_t)r * 32 + j];
    rinv[r] = 1.0f / s;
}

// ---------------- HMMA split-f16 GEMM (TERMS-configurable) --------------------
// C = A·B^T with A=(Ah[+Al]), B=(Bh[+Bl]) per TERMS (1/2/3).
// hh -> f32 acc; corrections -> shared f16 acc.
// CTA 128x128, K_TILE=32, 3-stage cp.async, 8 warps (64x32).
// OUT_MODE: 2 fp32+bias; 3 exp(acc/32) hi-only + row partials;
//           4 acc*rinv[row] split hi/lo; 5 hi-only.

#define NSTAGE   3
#define MAT_B    (128 * 80)
#define STAGE_B  (4 * MAT_B)
#define SMEM_B   (NSTAGE * STAGE_B)

template<int OUT_MODE, int TERMS>
__global__ __launch_bounds__(256, 1)
void gemm_hmma(const f16* __restrict__ Ah, const f16* __restrict__ Al,
               const f16* __restrict__ Bh, const f16* __restrict__ Bl,
               float* __restrict__ outF, f16* __restrict__ outHi, f16* __restrict__ outLo,
               const float* __restrict__ bias,
               float* __restrict__ spart, const float* __restrict__ rowscale,
               int M, int N, int K, long long sA, long long sB, long long sC)
{
    extern __shared__ __align__(16) char dsm[];
    __shared__ float part[128][4];
    const uint32_t sb = smem_u32(dsm);

    const int z = blockIdx.z;
    Ah += (size_t)z * sA;
    if (TERMS >= 2) Al += (size_t)z * sA;
    Bh += (size_t)z * sB;
    if (TERMS >= 3) Bl += (size_t)z * sB;

    const int tid = threadIdx.x;
    const int lane = tid & 31;
    const int warp = tid >> 5;
    const int m0 = blockIdx.y * 128;
    const int n0 = blockIdx.x * 128;

    const int wm0 = (warp & 1) * 64;
    const int wn0 = (warp >> 1) * 32;
    const int arow = lane & 15;
    const int acol = (lane >> 4) * 8;
    const int brow = lane & 7;
    const int bcol = ((lane >> 3) & 1) * 8;

    const int nk = K >> 5;

    const int ar0 = tid >> 2,          ac0 = (tid & 3);
    const int ar1 = (tid + 256) >> 2,  ac1 = ((tid + 256) & 3);

    auto load_stage = [&](int kt, int stg) {
        const uint32_t base = sb + stg * STAGE_B;
        const int kk = kt << 5;
        {
            uint32_t d = base + ar0 * 80 + ac0 * 16;
            const size_t ga = (size_t)(m0 + ar0) * K + kk + ac0 * 8;
            const size_t gb = (size_t)(n0 + ar0) * K + kk + ac0 * 8;
            cpa16(d,           Ah + ga);
            if (TERMS >= 2) cpa16(d + MAT_B, Al + ga);
            cpa16(d + 2*MAT_B, Bh + gb);
            if (TERMS >= 3) cpa16(d + 3*MAT_B, Bl + gb);
        }
        {
            uint32_t d = base + ar1 * 80 + ac1 * 16;
            const size_t ga = (size_t)(m0 + ar1) * K + kk + ac1 * 8;
            const size_t gb = (size_t)(n0 + ar1) * K + kk + ac1 * 8;
            cpa16(d,           Ah + ga);
            if (TERMS >= 2) cpa16(d + MAT_B, Al + ga);
            cpa16(d + 2*MAT_B, Bh + gb);
            if (TERMS >= 3) cpa16(d + 3*MAT_B, Bl + gb);
        }
        asm volatile("cp.async.commit_group;" ::: "memory");
    };

    float    hh[4][4][4];
    uint32_t cx[4][4][2];
#pragma unroll
    for (int t = 0; t < 4; t++)
#pragma unroll
        for (int u = 0; u < 4; u++) {
#pragma unroll
            for (int e = 0; e < 4; e++) hh[t][u][e] = 0.0f;
            cx[t][u][0] = 0u; cx[t][u][1] = 0u;
        }

    load_stage(0, 0);
    load_stage(1, 1);

    for (int kt = 0; kt < nk; kt++) {
        asm volatile("cp.async.wait_group 1;" ::: "memory");
        __syncthreads();

        if (kt + 2 < nk) load_stage(kt + 2, (kt + 2) % NSTAGE);
        else             asm volatile("cp.async.commit_group;" ::: "memory");

        const uint32_t base = sb + (kt % NSTAGE) * STAGE_B;

#pragma unroll
        for (int ks = 0; ks < 2; ks++) {
            const int kbyte = ks * 32;
            uint32_t ah[4][4], al[4][4], bh[4][2], bl[4][2];
#pragma unroll
            for (int t = 0; t < 4; t++) {
                uint32_t ad = base + (uint32_t)(wm0 + t*16 + arow) * 80 + kbyte + acol * 2;
                LDSM4(ah[t], ad);
                if (TERMS >= 2) LDSM4(al[t], ad + MAT_B);
            }
#pragma unroll
            for (int u = 0; u < 4; u++) {
                uint32_t bd = base + 2*MAT_B + (uint32_t)(wn0 + u*8 + brow) * 80 + kbyte + bcol * 2;
                LDSM2(bh[u], bd);
                if (TERMS >= 3) LDSM2(bl[u], bd + MAT_B);
            }
#pragma unroll
            for (int t = 0; t < 4; t++)
#pragma unroll
                for (int u = 0; u < 4; u++) MMA_F32ACC(hh[t][u], ah[t], bh[u]);
            if (TERMS >= 3) {
#pragma unroll
                for (int t = 0; t < 4; t++)
#pragma unroll
                    for (int u = 0; u < 4; u++) MMA_F16ACC(cx[t][u], ah[t], bl[u]);
            }
            if (TERMS >= 2) {
#pragma unroll
                for (int t = 0; t < 4; t++)
#pragma unroll
                    for (int u = 0; u < 4; u++) MMA_F16ACC(cx[t][u], al[t], bh[u]);
            }
        }
    }

    // ---- epilogue ----
    const size_t cbase = (size_t)z * sC;
#pragma unroll
    for (int t = 0; t < 4; t++) {
        const int gm = m0 + wm0 + t * 16 + (lane >> 2);
        float rs0 = 0.0f, rs1 = 0.0f;
        float rv0 = 1.0f, rv1 = 1.0f;
        if (OUT_MODE == 4) {
            rv0 = rowscale[(size_t)z * M + gm];
            rv1 = rowscale[(size_t)z * M + gm + 8];
        }
#pragma unroll
        for (int u = 0; u < 4; u++) {
            const int gn = n0 + wn0 + u * 8 + (lane & 3) * 2;
            float v00 = hh[t][u][0], v01 = hh[t][u][1];
            float v10 = hh[t][u][2], v11 = hh[t][u][3];
            if (TERMS >= 2) {
                float2 c01 = __half22float2(*(__half2*)&cx[t][u][0]);
                float2 c23 = __half22float2(*(__half2*)&cx[t][u][1]);
                v00 += c01.x; v01 += c01.y; v10 += c23.x; v11 += c23.y;
            }
            if (OUT_MODE == 2) {
                float b0 = bias[gn], b1 = bias[gn + 1];
                v00 += b0; v01 += b1; v10 += b0; v11 += b1;
            }
            if (OUT_MODE == 3) {
                v00 = __expf(v00 * 0.03125f);
                v01 = __expf(v01 * 0.03125f);
                v10 = __expf(v10 * 0.03125f);
                v11 = __expf(v11 * 0.03125f);
                rs0 += v00 + v01;
                rs1 += v10 + v11;
            }
            if (OUT_MODE == 4) {
                v00 *= rv0; v01 *= rv0; v10 *= rv1; v11 *= rv1;
            }
            if (OUT_MODE == 2) {
                *(float2*)(outF + cbase + (size_t)gm * N + gn) = make_float2(v00, v01);
                *(float2*)(outF + cbase + (size_t)(gm + 8) * N + gn) = make_float2(v10, v11);
            } else if (OUT_MODE == 3 || OUT_MODE == 5) {
                __half2 hp0; hp0.x = __float2half_rn(v00); hp0.y = __float2half_rn(v01);
                __half2 hp1; hp1.x = __float2half_rn(v10); hp1.y = __float2half_rn(v11);
                *(__half2*)(outHi + cbase + (size_t)gm * N + gn) = hp0;
                *(__half2*)(outHi + cbase + (size_t)(gm + 8) * N + gn) = hp1;
            } else {
                f16 h00 = __float2half_rn(v00), h01 = __float2half_rn(v01);
                f16 h10 = __float2half_rn(v10), h11 = __float2half_rn(v11);
                __half2 hp0; hp0.x = h00; hp0.y = h01;
                __half2 hp1; hp1.x = h10; hp1.y = h11;
                __half2 lp0; lp0.x = __float2half_rn(v00 - __half2float(h00));
                             lp0.y = __float2half_rn(v01 - __half2float(h01));
                __half2 lp1; lp1.x = __float2half_rn(v10 - __half2float(h10));
                             lp1.y = __float2half_rn(v11 - __half2float(h11));
                *(__half2*)(outHi + cbase + (size_t)gm * N + gn) = hp0;
                *(__half2*)(outHi + cbase + (size_t)(gm + 8) * N + gn) = hp1;
                *(__half2*)(outLo + cbase + (size_t)gm * N + gn) = lp0;
                *(__half2*)(outLo + cbase + (size_t)(gm + 8) * N + gn) = lp1;
            }
        }
        if (OUT_MODE == 3) {
            rs0 += __shfl_xor_sync(0xffffffffu, rs0, 1);
            rs0 += __shfl_xor_sync(0xffffffffu, rs0, 2);
            rs1 += __shfl_xor_sync(0xffffffffu, rs1, 1);
            rs1 += __shfl_xor_sync(0xffffffffu, rs1, 2);
            if ((lane & 3) == 0) {
                part[wm0 + t * 16 + (lane >> 2)][warp >> 1] = rs0;
                part[wm0 + t * 16 + (lane >> 2) + 8][warp >> 1] = rs1;
            }
        }
    }
    if (OUT_MODE == 3) {
        __syncthreads();
        if (tid < 128) {
            float s = part[tid][0] + part[tid][1] + part[tid][2] + part[tid][3];
            spart[((size_t)z * M + m0 + tid) * 32 + blockIdx.x] = s;
        }
    }
}

// ---------------- host ----------------
extern "C" void kernel_launch(void* const* d_in, const int* in_sizes, int n_in,
                              void* d_out, int out_size)
{
    const float* x  = (const float*)d_in[0];
    const float* y  = (const float*)d_in[1];
    const float* Wq = (const float*)d_in[2];
    const float* Wk = (const float*)d_in[3];
    const float* Wv = (const float*)d_in[4];
    const float* Wo = (const float*)d_in[5];
    const float* bo = (const float*)d_in[6];
    float* out = (float*)d_out;

#define GET(sym, var) void* var; cudaGetSymbolAddress(&var, sym)
    GET(g_xh, xh); GET(g_xl, xl); GET(g_yh, yh); GET(g_yl, yl);
    GET(g_wqh, wqh); GET(g_wkh, wkh); GET(g_wvh, wvh);
    GET(g_woh, woh); GET(g_wol, wol);
    GET(g_qh, qh); GET(g_kh, kh); GET(g_vh, vh); GET(g_vth, vth);
    GET(g_ph, ph); GET(g_ch, ch); GET(g_cl, cl);
    GET(g_spart, spart); GET(g_rinv, rinv);
#undef GET

    cudaFuncSetAttribute((void*)gemm_hmma<5,2>, cudaFuncAttributeMaxDynamicSharedMemorySize, SMEM_B);
    cudaFuncSetAttribute((void*)gemm_hmma<3,1>, cudaFuncAttributeMaxDynamicSharedMemorySize, SMEM_B);
    cudaFuncSetAttribute((void*)gemm_hmma<4,1>, cudaFuncAttributeMaxDynamicSharedMemorySize, SMEM_B);
    cudaFuncSetAttribute((void*)gemm_hmma<2,3>, cudaFuncAttributeMaxDynamicSharedMemorySize, SMEM_B);

    const int MBN = BATCH * NSEQ;            // 16384

    // splits (batched)
    {
        int n4 = BATCH * NSEQ * DDIM / 4;
        dim3 g1(n4 / 256, 1, 2);
        split_xy<<<g1, 256>>>((const float4*)x, (f16*)xh, (f16*)xl,
                              (const float4*)y, (f16*)yh, (f16*)yl, n4);
        int w4 = EDIM * DDIM / 4;
        dim3 g2(w4 / 256, 1, 4);
        split_w<<<g2, 256>>>((const float4*)Wq, (f16*)wqh,
                             (const float4*)Wk, (f16*)wkh,
                             (const float4*)Wv, (f16*)wvh,
                             (const float4*)Wo, (f16*)woh, (f16*)wol, w4);
    }

    // projections (2-term: input split x W-hi), hi-only output
    {
        dim3 grid(EDIM / 128, MBN / 128, 1);
        gemm_hmma<5,2><<<grid, 256, SMEM_B>>>((f16*)yh, (f16*)yl, (f16*)wqh, nullptr,
                                              nullptr, (f16*)qh, nullptr, nullptr,
                                              nullptr, nullptr, MBN, EDIM, DDIM, 0, 0, 0);
        gemm_hmma<5,2><<<grid, 256, SMEM_B>>>((f16*)xh, (f16*)xl, (f16*)wkh, nullptr,
                                              nullptr, (f16*)kh, nullptr, nullptr,
                                              nullptr, nullptr, MBN, EDIM, DDIM, 0, 0, 0);
        gemm_hmma<5,2><<<grid, 256, SMEM_B>>>((f16*)xh, (f16*)xl, (f16*)wvh, nullptr,
                                              nullptr, (f16*)vh, nullptr, nullptr,
                                              nullptr, nullptr, MBN, EDIM, DDIM, 0, 0, 0);
    }

    // scores+exp (1-term), hi-only E + row partials
    {
        dim3 grid(NSEQ / 128, NSEQ / 128, BATCH);
        gemm_hmma<3,1><<<grid, 256, SMEM_B>>>((f16*)qh, nullptr, (f16*)kh, nullptr,
                                              nullptr, (f16*)ph, nullptr, nullptr,
                                              (float*)spart, nullptr,
                                              NSEQ, NSEQ, EDIM,
                                              (long long)NSEQ * EDIM, (long long)NSEQ * EDIM,
                                              (long long)NSEQ * NSEQ);
    }

    // rinv = 1/rowsum
    rowsum_inv<<<MBN / 256, 256>>>((const float*)spart, (float*)rinv, MBN);

    // transpose V-hi
    {
        dim3 grid(EDIM / 64, NSEQ / 64, BATCH);
        transpose_k<<<grid, 256>>>((f16*)vh, (f16*)vth);
    }

    // ctx (1-term: Ph·Vh), ×rinv, split hi/lo output (feeds 3-term out GEMM)
    {
        dim3 grid(EDIM / 128, NSEQ / 128, BATCH);
        gemm_hmma<4,1><<<grid, 256, SMEM_B>>>((f16*)ph, nullptr, (f16*)vth, nullptr,
                                              nullptr, (f16*)ch, (f16*)cl, nullptr,
                                              nullptr, (const float*)rinv,
                                              NSEQ, EDIM, NSEQ,
                                              (long long)NSEQ * NSEQ, (long long)EDIM * NSEQ,
                                              (long long)NSEQ * EDIM);
    }

    // out = ctx @ Wo^T + bo (3-term)
    {
        dim3 grid(DDIM / 128, MBN / 128, 1);
        gemm_hmma<2,3><<<grid, 256, SMEM_B>>>((f16*)ch, (f16*)cl, (f16*)woh, (f16*)wol,
                                              out, nullptr, nullptr, bo,
                                              nullptr, nullptr, MBN, DDIM, EDIM, 0, 0, 0);
    }

    (void)in_sizes; (void)n_in; (void)out_size;
}

// round 12
// speedup vs baseline: 2.0303x; 1.1853x over previous
#include <cuda_runtime.h>
#include <cuda_fp16.h>
#include <stdint.h>

#define BATCH 4
#define NSEQ  4096
#define DDIM  1024
#define EDIM  1024

typedef __half f16;

// ---------------- scratch (device globals; no allocations allowed) -------------
__device__ f16 g_xh[(size_t)BATCH*NSEQ*DDIM];
__device__ f16 g_yh[(size_t)BATCH*NSEQ*DDIM];
__device__ f16 g_wqh[(size_t)EDIM*DDIM];
__device__ f16 g_wkh[(size_t)EDIM*DDIM];
__device__ f16 g_wvh[(size_t)EDIM*DDIM];
__device__ f16 g_woh[(size_t)DDIM*EDIM];
__device__ f16 g_qh[(size_t)BATCH*NSEQ*EDIM];
__device__ f16 g_kh[(size_t)BATCH*NSEQ*EDIM];
__device__ f16 g_vh[(size_t)BATCH*NSEQ*EDIM];
__device__ f16 g_vth[(size_t)BATCH*EDIM*NSEQ];
__device__ f16 g_ph[(size_t)BATCH*NSEQ*NSEQ];
__device__ f16 g_ch[(size_t)BATCH*NSEQ*EDIM], g_cl[(size_t)BATCH*NSEQ*EDIM];
__device__ float g_spart[(size_t)BATCH*NSEQ*32];
__device__ float g_rinv[(size_t)BATCH*NSEQ];

// ---------------- helpers ----------------
__device__ __forceinline__ uint32_t smem_u32(const void* p) {
    uint32_t a;
    asm("{ .reg .u64 t; cvta.to.shared.u64 t, %1; cvt.u32.u64 %0, t; }" : "=r"(a) : "l"(p));
    return a;
}
__device__ __forceinline__ void cpa16(uint32_t dst, const void* src) {
    asm volatile("cp.async.cg.shared.global [%0], [%1], 16;" :: "r"(dst), "l"(src));
}

#define MMA_F32ACC(c, a, b) \
    asm volatile("mma.sync.aligned.m16n8k16.row.col.f32.f16.f16.f32 " \
                 "{%0,%1,%2,%3},{%4,%5,%6,%7},{%8,%9},{%0,%1,%2,%3};\n" \
                 : "+f"(c[0]), "+f"(c[1]), "+f"(c[2]), "+f"(c[3]) \
                 : "r"(a[0]), "r"(a[1]), "r"(a[2]), "r"(a[3]), "r"(b[0]), "r"(b[1]))

#define MMA_F16ACC(c, a, b) \
    asm volatile("mma.sync.aligned.m16n8k16.row.col.f16.f16.f16.f16 " \
                 "{%0,%1},{%2,%3,%4,%5},{%6,%7},{%0,%1};\n" \
                 : "+r"(c[0]), "+r"(c[1]) \
                 : "r"(a[0]), "r"(a[1]), "r"(a[2]), "r"(a[3]), "r"(b[0]), "r"(b[1]))

#define LDSM4(r, a) \
    asm volatile("ldmatrix.sync.aligned.m8n8.x4.shared.b16 {%0,%1,%2,%3}, [%4];\n" \
                 : "=r"((r)[0]), "=r"((r)[1]), "=r"((r)[2]), "=r"((r)[3]) : "r"(a))
#define LDSM2(r, a) \
    asm volatile("ldmatrix.sync.aligned.m8n8.x2.shared.b16 {%0,%1}, [%2];\n" \
                 : "=r"((r)[0]), "=r"((r)[1]) : "r"(a))

// ---------------- fp32 -> f16 hi (batched over z) ----------------
__device__ __forceinline__ void to_f16_one(const float4* src, f16* hi, int i)
{
    float4 v = src[i];
    __half2 h01; h01.x = __float2half_rn(v.x); h01.y = __float2half_rn(v.y);
    __half2 h23; h23.x = __float2half_rn(v.z); h23.y = __float2half_rn(v.w);
    reinterpret_cast<__half2*>(hi)[2*i]   = h01;
    reinterpret_cast<__half2*>(hi)[2*i+1] = h23;
}

__global__ void conv_xy(const float4* __restrict__ x, f16* xh,
                        const float4* __restrict__ y, f16* yh, int n4)
{
    int i = blockIdx.x * blockDim.x + threadIdx.x;
    if (i >= n4) return;
    if (blockIdx.z == 0) to_f16_one(x, xh, i);
    else                 to_f16_one(y, yh, i);
}

__global__ void conv_w(const float4* __restrict__ wq, f16* wqh,
                       const float4* __restrict__ wk, f16* wkh,
                       const float4* __restrict__ wv, f16* wvh,
                       const float4* __restrict__ wo, f16* woh, int n4)
{
    int i = blockIdx.x * blockDim.x + threadIdx.x;
    if (i >= n4) return;
    switch (blockIdx.z) {
        case 0: to_f16_one(wq, wqh, i); break;
        case 1: to_f16_one(wk, wkh, i); break;
        case 2: to_f16_one(wv, wvh, i); break;
        default: to_f16_one(wo, woh, i); break;
    }
}

// ---------------- f16 transpose per batch: in [NSEQ, EDIM] -> out [EDIM, NSEQ] ---
__global__ __launch_bounds__(256)
void transpose_k(const f16* __restrict__ in, f16* __restrict__ out)
{
    __shared__ f16 t[64][72];
    const int z = blockIdx.z;
    in  += (size_t)z * NSEQ * EDIM;
    out += (size_t)z * EDIM * NSEQ;
    const int x0 = blockIdx.x * 64;
    const int y0 = blockIdx.y * 64;
    const int tid = threadIdx.x;
    const int r = tid >> 3, c = (tid & 7) * 8;
#pragma unroll
    for (int i = 0; i < 2; i++) {
        uint4 v = *(const uint4*)(in + (size_t)(y0 + r + 32*i) * EDIM + x0 + c);
        *(uint4*)&t[r + 32*i][c] = v;
    }
    __syncthreads();
#pragma unroll
    for (int i = 0; i < 2; i++) {
        int orow = r + 32*i;
        f16 tmp[8];
#pragma unroll
        for (int j = 0; j < 8; j++) tmp[j] = t[c + j][orow];
        *(uint4*)(out + (size_t)(x0 + orow) * NSEQ + y0 + c) = *(uint4*)tmp;
    }
}

// ---------------- rowsum partials -> 1/sum ----------------
__global__ void rowsum_inv(const float* __restrict__ spart, float* __restrict__ rinv, int nrows)
{
    int r = blockIdx.x * 256 + threadIdx.x;
    if (r >= nrows) return;
    float s = 0.0f;
#pragma unroll
    for (int j = 0; j < 32; j++) s += spart[(size_t)r * 32 + j];
    rinv[r] = 1.0f / s;
}

// ---------------- HMMA split-f16 GEMM (TERMS-configurable) --------------------
// C = A·B^T per TERMS: 1: Ah·Bh; 2: +Al·Bh; 3: +Ah·Bl.
// hh -> f32 acc; corrections -> shared f16 acc.
// CTA 128x128, K_TILE=32, 3-stage cp.async, 8 warps (64x32).
// OUT_MODE: 2 fp32+bias; 3 exp(acc/32) hi-only + row partials;
//           4 acc*rinv[row] split hi/lo; 5 hi-only.

#define NSTAGE   3
#define MAT_B    (128 * 80)
#define STAGE_B  (4 * MAT_B)
#define SMEM_B   (NSTAGE * STAGE_B)

template<int OUT_MODE, int TERMS>
__global__ __launch_bounds__(256, 1)
void gemm_hmma(const f16* __restrict__ Ah, const f16* __restrict__ Al,
               const f16* __restrict__ Bh, const f16* __restrict__ Bl,
               float* __restrict__ outF, f16* __restrict__ outHi, f16* __restrict__ outLo,
               const float* __restrict__ bias,
               float* __restrict__ spart, const float* __restrict__ rowscale,
               int M, int N, int K, long long sA, long long sB, long long sC)
{
    extern __shared__ __align__(16) char dsm[];
    __shared__ float part[128][4];
    const uint32_t sb = smem_u32(dsm);

    const int z = blockIdx.z;
    Ah += (size_t)z * sA;
    if (TERMS >= 2) Al += (size_t)z * sA;
    Bh += (size_t)z * sB;
    if (TERMS >= 3) Bl += (size_t)z * sB;

    const int tid = threadIdx.x;
    const int lane = tid & 31;
    const int warp = tid >> 5;
    const int m0 = blockIdx.y * 128;
    const int n0 = blockIdx.x * 128;

    const int wm0 = (warp & 1) * 64;
    const int wn0 = (warp >> 1) * 32;
    const int arow = lane & 15;
    const int acol = (lane >> 4) * 8;
    const int brow = lane & 7;
    const int bcol = ((lane >> 3) & 1) * 8;

    const int nk = K >> 5;

    const int ar0 = tid >> 2,          ac0 = (tid & 3);
    const int ar1 = (tid + 256) >> 2,  ac1 = ((tid + 256) & 3);

    auto load_stage = [&](int kt, int stg) {
        const uint32_t base = sb + stg * STAGE_B;
        const int kk = kt << 5;
        {
            uint32_t d = base + ar0 * 80 + ac0 * 16;
            const size_t ga = (size_t)(m0 + ar0) * K + kk + ac0 * 8;
            const size_t gb = (size_t)(n0 + ar0) * K + kk + ac0 * 8;
            cpa16(d,           Ah + ga);
            if (TERMS >= 2) cpa16(d + MAT_B, Al + ga);
            cpa16(d + 2*MAT_B, Bh + gb);
            if (TERMS >= 3) cpa16(d + 3*MAT_B, Bl + gb);
        }
        {
            uint32_t d = base + ar1 * 80 + ac1 * 16;
            const size_t ga = (size_t)(m0 + ar1) * K + kk + ac1 * 8;
            const size_t gb = (size_t)(n0 + ar1) * K + kk + ac1 * 8;
            cpa16(d,           Ah + ga);
            if (TERMS >= 2) cpa16(d + MAT_B, Al + ga);
            cpa16(d + 2*MAT_B, Bh + gb);
            if (TERMS >= 3) cpa16(d + 3*MAT_B, Bl + gb);
        }
        asm volatile("cp.async.commit_group;" ::: "memory");
    };

    float    hh[4][4][4];
    uint32_t cx[4][4][2];
#pragma unroll
    for (int t = 0; t < 4; t++)
#pragma unroll
        for (int u = 0; u < 4; u++) {
#pragma unroll
            for (int e = 0; e < 4; e++) hh[t][u][e] = 0.0f;
            cx[t][u][0] = 0u; cx[t][u][1] = 0u;
        }

    load_stage(0, 0);
    load_stage(1, 1);

    for (int kt = 0; kt < nk; kt++) {
        asm volatile("cp.async.wait_group 1;" ::: "memory");
        __syncthreads();

        if (kt + 2 < nk) load_stage(kt + 2, (kt + 2) % NSTAGE);
        else             asm volatile("cp.async.commit_group;" ::: "memory");

        const uint32_t base = sb + (kt % NSTAGE) * STAGE_B;

#pragma unroll
        for (int ks = 0; ks < 2; ks++) {
            const int kbyte = ks * 32;
            uint32_t ah[4][4], al[4][4], bh[4][2], bl[4][2];
#pragma unroll
            for (int t = 0; t < 4; t++) {
                uint32_t ad = base + (uint32_t)(wm0 + t*16 + arow) * 80 + kbyte + acol * 2;
                LDSM4(ah[t], ad);
                if (TERMS >= 2) LDSM4(al[t], ad + MAT_B);
            }
#pragma unroll
            for (int u = 0; u < 4; u++) {
                uint32_t bd = base + 2*MAT_B + (uint32_t)(wn0 + u*8 + brow) * 80 + kbyte + bcol * 2;
                LDSM2(bh[u], bd);
                if (TERMS >= 3) LDSM2(bl[u], bd + MAT_B);
            }
#pragma unroll
            for (int t = 0; t < 4; t++)
#pragma unroll
                for (int u = 0; u < 4; u++) MMA_F32ACC(hh[t][u], ah[t], bh[u]);
            if (TERMS >= 3) {
#pragma unroll
                for (int t = 0; t < 4; t++)
#pragma unroll
                    for (int u = 0; u < 4; u++) MMA_F16ACC(cx[t][u], ah[t], bl[u]);
            }
            if (TERMS >= 2) {
#pragma unroll
                for (int t = 0; t < 4; t++)
#pragma unroll
                    for (int u = 0; u < 4; u++) MMA_F16ACC(cx[t][u], al[t], bh[u]);
            }
        }
    }

    // ---- epilogue ----
    const size_t cbase = (size_t)z * sC;
#pragma unroll
    for (int t = 0; t < 4; t++) {
        const int gm = m0 + wm0 + t * 16 + (lane >> 2);
        float rs0 = 0.0f, rs1 = 0.0f;
        float rv0 = 1.0f, rv1 = 1.0f;
        if (OUT_MODE == 4) {
            rv0 = rowscale[(size_t)z * M + gm];
            rv1 = rowscale[(size_t)z * M + gm + 8];
        }
#pragma unroll
        for (int u = 0; u < 4; u++) {
            const int gn = n0 + wn0 + u * 8 + (lane & 3) * 2;
            float v00 = hh[t][u][0], v01 = hh[t][u][1];
            float v10 = hh[t][u][2], v11 = hh[t][u][3];
            if (TERMS >= 2) {
                float2 c01 = __half22float2(*(__half2*)&cx[t][u][0]);
                float2 c23 = __half22float2(*(__half2*)&cx[t][u][1]);
                v00 += c01.x; v01 += c01.y; v10 += c23.x; v11 += c23.y;
            }
            if (OUT_MODE == 2) {
                float b0 = bias[gn], b1 = bias[gn + 1];
                v00 += b0; v01 += b1; v10 += b0; v11 += b1;
            }
            if (OUT_MODE == 3) {
                v00 = __expf(v00 * 0.03125f);
                v01 = __expf(v01 * 0.03125f);
                v10 = __expf(v10 * 0.03125f);
                v11 = __expf(v11 * 0.03125f);
                rs0 += v00 + v01;
                rs1 += v10 + v11;
            }
            if (OUT_MODE == 4) {
                v00 *= rv0; v01 *= rv0; v10 *= rv1; v11 *= rv1;
            }
            if (OUT_MODE == 2) {
                *(float2*)(outF + cbase + (size_t)gm * N + gn) = make_float2(v00, v01);
                *(float2*)(outF + cbase + (size_t)(gm + 8) * N + gn) = make_float2(v10, v11);
            } else if (OUT_MODE == 3 || OUT_MODE == 5) {
                __half2 hp0; hp0.x = __float2half_rn(v00); hp0.y = __float2half_rn(v01);
                __half2 hp1; hp1.x = __float2half_rn(v10); hp1.y = __float2half_rn(v11);
                *(__half2*)(outHi + cbase + (size_t)gm * N + gn) = hp0;
                *(__half2*)(outHi + cbase + (size_t)(gm + 8) * N + gn) = hp1;
            } else {
                f16 h00 = __float2half_rn(v00), h01 = __float2half_rn(v01);
                f16 h10 = __float2half_rn(v10), h11 = __float2half_rn(v11);
                __half2 hp0; hp0.x = h00; hp0.y = h01;
                __half2 hp1; hp1.x = h10; hp1.y = h11;
                __half2 lp0; lp0.x = __float2half_rn(v00 - __half2float(h00));
                             lp0.y = __float2half_rn(v01 - __half2float(h01));
                __half2 lp1; lp1.x = __float2half_rn(v10 - __half2float(h10));
                             lp1.y = __float2half_rn(v11 - __half2float(h11));
                *(__half2*)(outHi + cbase + (size_t)gm * N + gn) = hp0;
                *(__half2*)(outHi + cbase + (size_t)(gm + 8) * N + gn) = hp1;
                *(__half2*)(outLo + cbase + (size_t)gm * N + gn) = lp0;
                *(__half2*)(outLo + cbase + (size_t)(gm + 8) * N + gn) = lp1;
            }
        }
        if (OUT_MODE == 3) {
            rs0 += __shfl_xor_sync(0xffffffffu, rs0, 1);
            rs0 += __shfl_xor_sync(0xffffffffu, rs0, 2);
            rs1 += __shfl_xor_sync(0xffffffffu, rs1, 1);
            rs1 += __shfl_xor_sync(0xffffffffu, rs1, 2);
            if ((lane & 3) == 0) {
                part[wm0 + t * 16 + (lane >> 2)][warp >> 1] = rs0;
                part[wm0 + t * 16 + (lane >> 2) + 8][warp >> 1] = rs1;
            }
        }
    }
    if (OUT_MODE == 3) {
        __syncthreads();
        if (tid < 128) {
            float s = part[tid][0] + part[tid][1] + part[tid][2] + part[tid][3];
            spart[((size_t)z * M + m0 + tid) * 32 + blockIdx.x] = s;
        }
    }
}

// ---------------- host ----------------
extern "C" void kernel_launch(void* const* d_in, const int* in_sizes, int n_in,
                              void* d_out, int out_size)
{
    const float* x  = (const float*)d_in[0];
    const float* y  = (const float*)d_in[1];
    const float* Wq = (const float*)d_in[2];
    const float* Wk = (const float*)d_in[3];
    const float* Wv = (const float*)d_in[4];
    const float* Wo = (const float*)d_in[5];
    const float* bo = (const float*)d_in[6];
    float* out = (float*)d_out;

#define GET(sym, var) void* var; cudaGetSymbolAddress(&var, sym)
    GET(g_xh, xh); GET(g_yh, yh);
    GET(g_wqh, wqh); GET(g_wkh, wkh); GET(g_wvh, wvh); GET(g_woh, woh);
    GET(g_qh, qh); GET(g_kh, kh); GET(g_vh, vh); GET(g_vth, vth);
    GET(g_ph, ph); GET(g_ch, ch); GET(g_cl, cl);
    GET(g_spart, spart); GET(g_rinv, rinv);
#undef GET

    cudaFuncSetAttribute((void*)gemm_hmma<5,1>, cudaFuncAttributeMaxDynamicSharedMemorySize, SMEM_B);
    cudaFuncSetAttribute((void*)gemm_hmma<3,1>, cudaFuncAttributeMaxDynamicSharedMemorySize, SMEM_B);
    cudaFuncSetAttribute((void*)gemm_hmma<4,1>, cudaFuncAttributeMaxDynamicSharedMemorySize, SMEM_B);
    cudaFuncSetAttribute((void*)gemm_hmma<2,2>, cudaFuncAttributeMaxDynamicSharedMemorySize, SMEM_B);

    const int MBN = BATCH * NSEQ;            // 16384

    // f32 -> f16 conversions (hi only; batched)
    {
        int n4 = BATCH * NSEQ * DDIM / 4;
        dim3 g1(n4 / 256, 1, 2);
        conv_xy<<<g1, 256>>>((const float4*)x, (f16*)xh,
                             (const float4*)y, (f16*)yh, n4);
        int w4 = EDIM * DDIM / 4;
        dim3 g2(w4 / 256, 1, 4);
        conv_w<<<g2, 256>>>((const float4*)Wq, (f16*)wqh,
                            (const float4*)Wk, (f16*)wkh,
                            (const float4*)Wv, (f16*)wvh,
                            (const float4*)Wo, (f16*)woh, w4);
    }

    // projections (1-term: hi x hi), hi-only output
    {
        dim3 grid(EDIM / 128, MBN / 128, 1);
        gemm_hmma<5,1><<<grid, 256, SMEM_B>>>((f16*)yh, nullptr, (f16*)wqh, nullptr,
                                              nullptr, (f16*)qh, nullptr, nullptr,
                                              nullptr, nullptr, MBN, EDIM, DDIM, 0, 0, 0);
        gemm_hmma<5,1><<<grid, 256, SMEM_B>>>((f16*)xh, nullptr, (f16*)wkh, nullptr,
                                              nullptr, (f16*)kh, nullptr, nullptr,
                                              nullptr, nullptr, MBN, EDIM, DDIM, 0, 0, 0);
        gemm_hmma<5,1><<<grid, 256, SMEM_B>>>((f16*)xh, nullptr, (f16*)wvh, nullptr,
                                              nullptr, (f16*)vh, nullptr, nullptr,
                                              nullptr, nullptr, MBN, EDIM, DDIM, 0, 0, 0);
    }

    // scores+exp (1-term), hi-only E + row partials
    {
        dim3 grid(NSEQ / 128, NSEQ / 128, BATCH);
        gemm_hmma<3,1><<<grid, 256, SMEM_B>>>((f16*)qh, nullptr, (f16*)kh, nullptr,
                                              nullptr, (f16*)ph, nullptr, nullptr,
                                              (float*)spart, nullptr,
                                              NSEQ, NSEQ, EDIM,
                                              (long long)NSEQ * EDIM, (long long)NSEQ * EDIM,
                                              (long long)NSEQ * NSEQ);
    }

    // rinv = 1/rowsum
    rowsum_inv<<<MBN / 256, 256>>>((const float*)spart, (float*)rinv, MBN);

    // transpose V
    {
        dim3 grid(EDIM / 64, NSEQ / 64, BATCH);
        transpose_k<<<grid, 256>>>((f16*)vh, (f16*)vth);
    }

    // ctx (1-term: Ph·Vh), ×rinv, split hi/lo output (feeds 2-term out GEMM)
    {
        dim3 grid(EDIM / 128, NSEQ / 128, BATCH);
        gemm_hmma<4,1><<<grid, 256, SMEM_B>>>((f16*)ph, nullptr, (f16*)vth, nullptr,
                                              nullptr, (f16*)ch, (f16*)cl, nullptr,
                                              nullptr, (const float*)rinv,
                                              NSEQ, EDIM, NSEQ,
                                              (long long)NSEQ * NSEQ, (long long)EDIM * NSEQ,
                                              (long long)NSEQ * EDIM);
    }

    // out = ctx @ Wo^T + bo (2-term: ctx split x Wo-hi)
    {
        dim3 grid(DDIM / 128, MBN / 128, 1);
        gemm_hmma<2,2><<<grid, 256, SMEM_B>>>((f16*)ch, (f16*)cl, (f16*)woh, nullptr,
                                              out, nullptr, nullptr, bo,
                                              nullptr, nullptr, MBN, DDIM, EDIM, 0, 0, 0);
    }

    (void)in_sizes; (void)n_in; (void)out_size;
}

// round 13
// speedup vs baseline: 2.3163x; 1.1409x over previous
#include <cuda_runtime.h>
#include <cuda_fp16.h>
#include <stdint.h>

#define BATCH 4
#define NSEQ  4096
#define DDIM  1024
#define EDIM  1024

typedef __half f16;

// ---------------- scratch (device globals; no allocations allowed) -------------
__device__ f16 g_xh[(size_t)BATCH*NSEQ*DDIM];
__device__ f16 g_yh[(size_t)BATCH*NSEQ*DDIM];
__device__ f16 g_wqh[(size_t)EDIM*DDIM];
__device__ f16 g_wkh[(size_t)EDIM*DDIM];
__device__ f16 g_wvh[(size_t)EDIM*DDIM];
__device__ f16 g_woh[(size_t)DDIM*EDIM];
__device__ f16 g_qh[(size_t)BATCH*NSEQ*EDIM];
__device__ f16 g_kh[(size_t)BATCH*NSEQ*EDIM];
__device__ f16 g_vh[(size_t)BATCH*NSEQ*EDIM];
__device__ f16 g_vth[(size_t)BATCH*EDIM*NSEQ];
__device__ f16 g_ph[(size_t)BATCH*NSEQ*NSEQ];
__device__ f16 g_ch[(size_t)BATCH*NSEQ*EDIM];
__device__ float g_spart[(size_t)BATCH*NSEQ*16];
__device__ float g_rinv[(size_t)BATCH*NSEQ];

// ---------------- helpers ----------------
__device__ __forceinline__ uint32_t smem_u32(const void* p) {
    uint32_t a;
    asm("{ .reg .u64 t; cvta.to.shared.u64 t, %1; cvt.u32.u64 %0, t; }" : "=r"(a) : "l"(p));
    return a;
}
__device__ __forceinline__ void cpa16(uint32_t dst, const void* src) {
    asm volatile("cp.async.cg.shared.global [%0], [%1], 16;" :: "r"(dst), "l"(src));
}

#define MMA_F32ACC(c, a, b) \
    asm volatile("mma.sync.aligned.m16n8k16.row.col.f32.f16.f16.f32 " \
                 "{%0,%1,%2,%3},{%4,%5,%6,%7},{%8,%9},{%0,%1,%2,%3};\n" \
                 : "+f"(c[0]), "+f"(c[1]), "+f"(c[2]), "+f"(c[3]) \
                 : "r"(a[0]), "r"(a[1]), "r"(a[2]), "r"(a[3]), "r"(b[0]), "r"(b[1]))

#define LDSM4(r, a) \
    asm volatile("ldmatrix.sync.aligned.m8n8.x4.shared.b16 {%0,%1,%2,%3}, [%4];\n" \
                 : "=r"((r)[0]), "=r"((r)[1]), "=r"((r)[2]), "=r"((r)[3]) : "r"(a))
#define LDSM2(r, a) \
    asm volatile("ldmatrix.sync.aligned.m8n8.x2.shared.b16 {%0,%1}, [%2];\n" \
                 : "=r"((r)[0]), "=r"((r)[1]) : "r"(a))

// ---------------- fp32 -> f16 (batched over z) ----------------
__device__ __forceinline__ void to_f16_one(const float4* src, f16* hi, int i)
{
    float4 v = src[i];
    __half2 h01; h01.x = __float2half_rn(v.x); h01.y = __float2half_rn(v.y);
    __half2 h23; h23.x = __float2half_rn(v.z); h23.y = __float2half_rn(v.w);
    reinterpret_cast<__half2*>(hi)[2*i]   = h01;
    reinterpret_cast<__half2*>(hi)[2*i+1] = h23;
}

__global__ void conv_xy(const float4* __restrict__ x, f16* xh,
                        const float4* __restrict__ y, f16* yh, int n4)
{
    int i = blockIdx.x * blockDim.x + threadIdx.x;
    if (i >= n4) return;
    if (blockIdx.z == 0) to_f16_one(x, xh, i);
    else                 to_f16_one(y, yh, i);
}

__global__ void conv_w(const float4* __restrict__ wq, f16* wqh,
                       const float4* __restrict__ wk, f16* wkh,
                       const float4* __restrict__ wv, f16* wvh,
                       const float4* __restrict__ wo, f16* woh, int n4)
{
    int i = blockIdx.x * blockDim.x + threadIdx.x;
    if (i >= n4) return;
    switch (blockIdx.z) {
        case 0: to_f16_one(wq, wqh, i); break;
        case 1: to_f16_one(wk, wkh, i); break;
        case 2: to_f16_one(wv, wvh, i); break;
        default: to_f16_one(wo, woh, i); break;
    }
}

// ---------------- f16 transpose per batch: [NSEQ, EDIM] -> [EDIM, NSEQ] -------
__global__ __launch_bounds__(256)
void transpose_k(const f16* __restrict__ in, f16* __restrict__ out)
{
    __shared__ f16 t[64][72];
    const int z = blockIdx.z;
    in  += (size_t)z * NSEQ * EDIM;
    out += (size_t)z * EDIM * NSEQ;
    const int x0 = blockIdx.x * 64;
    const int y0 = blockIdx.y * 64;
    const int tid = threadIdx.x;
    const int r = tid >> 3, c = (tid & 7) * 8;
#pragma unroll
    for (int i = 0; i < 2; i++) {
        uint4 v = *(const uint4*)(in + (size_t)(y0 + r + 32*i) * EDIM + x0 + c);
        *(uint4*)&t[r + 32*i][c] = v;
    }
    __syncthreads();
#pragma unroll
    for (int i = 0; i < 2; i++) {
        int orow = r + 32*i;
        f16 tmp[8];
#pragma unroll
        for (int j = 0; j < 8; j++) tmp[j] = t[c + j][orow];
        *(uint4*)(out + (size_t)(x0 + orow) * NSEQ + y0 + c) = *(uint4*)tmp;
    }
}

// ---------------- rowsum partials -> 1/sum ----------------
__global__ void rowsum_inv(const float* __restrict__ spart, float* __restrict__ rinv, int nrows)
{
    int r = blockIdx.x * 256 + threadIdx.x;
    if (r >= nrows) return;
    float s = 0.0f;
#pragma unroll
    for (int j = 0; j < 16; j++) s += spart[(size_t)r * 16 + j];
    rinv[r] = 1.0f / s;
}

// ---------------- 1-term f16 HMMA GEMM: C = Ah·Bh^T ---------------------------
// CTA tile 128 (M) x 256 (N), K_TILE=32, 3-stage cp.async, 8 warps (64x64).
// OUT_MODE: 2 fp32+bias; 3 exp(acc/32) hi + row partials; 5 hi-only;
//           6 acc*rinv[row] hi-only.

#define NSTAGE   3
#define MAT_A    (128 * 80)
#define MAT_BB   (256 * 80)
#define OFF_B    (MAT_A)
#define STAGE_B  (MAT_A + MAT_BB)            // 30720
#define SMEM_B   (NSTAGE * STAGE_B)          // 92160

template<int OUT_MODE>
__global__ __launch_bounds__(256, 1)
void gemm1(const f16* __restrict__ Ah, const f16* __restrict__ Bh,
           float* __restrict__ outF, f16* __restrict__ outHi,
           const float* __restrict__ bias,
           float* __restrict__ spart, const float* __restrict__ rowscale,
           int M, int N, int K, long long sA, long long sB, long long sC)
{
    extern __shared__ __align__(16) char dsm[];
    __shared__ float part[128][4];
    const uint32_t sb = smem_u32(dsm);

    const int z = blockIdx.z;
    Ah += (size_t)z * sA;
    Bh += (size_t)z * sB;

    const int tid = threadIdx.x;
    const int lane = tid & 31;
    const int warp = tid >> 5;
    const int m0 = blockIdx.y * 128;
    const int n0 = blockIdx.x * 256;

    const int wm0 = (warp & 1) * 64;          // 2 warps along M
    const int wn0 = (warp >> 1) * 64;         // 4 warps along N
    const int arow = lane & 15;
    const int acol = (lane >> 4) * 8;
    const int brow = lane & 7;
    const int bcol = ((lane >> 3) & 1) * 8;

    const int nk = K >> 5;

    const int ar0 = tid >> 2,          ac0 = (tid & 3);
    const int ar1 = (tid + 256) >> 2,  ac1 = ((tid + 256) & 3);

    auto load_stage = [&](int kt, int stg) {
        const uint32_t base = sb + stg * STAGE_B;
        const int kk = kt << 5;
        {
            uint32_t d = base + ar0 * 80 + ac0 * 16;
            cpa16(d, Ah + (size_t)(m0 + ar0) * K + kk + ac0 * 8);
        }
        {
            uint32_t d = base + ar1 * 80 + ac1 * 16;
            cpa16(d, Ah + (size_t)(m0 + ar1) * K + kk + ac1 * 8);
        }
#pragma unroll
        for (int i = 0; i < 4; i++) {
            const int idx = tid + 256 * i;
            const int br = idx >> 2, bc = idx & 3;
            uint32_t d = base + OFF_B + br * 80 + bc * 16;
            cpa16(d, Bh + (size_t)(n0 + br) * K + kk + bc * 8);
        }
        asm volatile("cp.async.commit_group;" ::: "memory");
    };

    float acc[4][8][4];
#pragma unroll
    for (int t = 0; t < 4; t++)
#pragma unroll
        for (int u = 0; u < 8; u++)
#pragma unroll
            for (int e = 0; e < 4; e++) acc[t][u][e] = 0.0f;

    load_stage(0, 0);
    load_stage(1, 1);

    for (int kt = 0; kt < nk; kt++) {
        asm volatile("cp.async.wait_group 1;" ::: "memory");
        __syncthreads();

        if (kt + 2 < nk) load_stage(kt + 2, (kt + 2) % NSTAGE);
        else             asm volatile("cp.async.commit_group;" ::: "memory");

        const uint32_t base = sb + (kt % NSTAGE) * STAGE_B;

#pragma unroll
        for (int ks = 0; ks < 2; ks++) {
            const int kbyte = ks * 32;
            uint32_t ah[4][4], bh[8][2];
#pragma unroll
            for (int t = 0; t < 4; t++) {
                uint32_t ad = base + (uint32_t)(wm0 + t*16 + arow) * 80 + kbyte + acol * 2;
                LDSM4(ah[t], ad);
            }
#pragma unroll
            for (int u = 0; u < 8; u++) {
                uint32_t bd = base + OFF_B + (uint32_t)(wn0 + u*8 + brow) * 80 + kbyte + bcol * 2;
                LDSM2(bh[u], bd);
            }
#pragma unroll
            for (int t = 0; t < 4; t++)
#pragma unroll
                for (int u = 0; u < 8; u++) MMA_F32ACC(acc[t][u], ah[t], bh[u]);
        }
    }

    // ---- epilogue ----
    const size_t cbase = (size_t)z * sC;
#pragma unroll
    for (int t = 0; t < 4; t++) {
        const int gm = m0 + wm0 + t * 16 + (lane >> 2);
        float rs0 = 0.0f, rs1 = 0.0f;
        float rv0 = 1.0f, rv1 = 1.0f;
        if (OUT_MODE == 6) {
            rv0 = rowscale[(size_t)z * M + gm];
            rv1 = rowscale[(size_t)z * M + gm + 8];
        }
#pragma unroll
        for (int u = 0; u < 8; u++) {
            const int gn = n0 + wn0 + u * 8 + (lane & 3) * 2;
            float v00 = acc[t][u][0], v01 = acc[t][u][1];
            float v10 = acc[t][u][2], v11 = acc[t][u][3];
            if (OUT_MODE == 2) {
                float b0 = bias[gn], b1 = bias[gn + 1];
                v00 += b0; v01 += b1; v10 += b0; v11 += b1;
            }
            if (OUT_MODE == 3) {
                v00 = __expf(v00 * 0.03125f);
                v01 = __expf(v01 * 0.03125f);
                v10 = __expf(v10 * 0.03125f);
                v11 = __expf(v11 * 0.03125f);
                rs0 += v00 + v01;
                rs1 += v10 + v11;
            }
            if (OUT_MODE == 6) {
                v00 *= rv0; v01 *= rv0; v10 *= rv1; v11 *= rv1;
            }
            if (OUT_MODE == 2) {
                *(float2*)(outF + cbase + (size_t)gm * N + gn) = make_float2(v00, v01);
                *(float2*)(outF + cbase + (size_t)(gm + 8) * N + gn) = make_float2(v10, v11);
            } else {
                __half2 hp0; hp0.x = __float2half_rn(v00); hp0.y = __float2half_rn(v01);
                __half2 hp1; hp1.x = __float2half_rn(v10); hp1.y = __float2half_rn(v11);
                *(__half2*)(outHi + cbase + (size_t)gm * N + gn) = hp0;
                *(__half2*)(outHi + cbase + (size_t)(gm + 8) * N + gn) = hp1;
            }
        }
        if (OUT_MODE == 3) {
            rs0 += __shfl_xor_sync(0xffffffffu, rs0, 1);
            rs0 += __shfl_xor_sync(0xffffffffu, rs0, 2);
            rs1 += __shfl_xor_sync(0xffffffffu, rs1, 1);
            rs1 += __shfl_xor_sync(0xffffffffu, rs1, 2);
            if ((lane & 3) == 0) {
                part[wm0 + t * 16 + (lane >> 2)][warp >> 1] = rs0;
                part[wm0 + t * 16 + (lane >> 2) + 8][warp >> 1] = rs1;
            }
        }
    }
    if (OUT_MODE == 3) {
        __syncthreads();
        if (tid < 128) {
            float s = part[tid][0] + part[tid][1] + part[tid][2] + part[tid][3];
            spart[((size_t)z * M + m0 + tid) * 16 + blockIdx.x] = s;
        }
    }
}

// ---------------- host ----------------
extern "C" void kernel_launch(void* const* d_in, const int* in_sizes, int n_in,
                              void* d_out, int out_size)
{
    const float* x  = (const float*)d_in[0];
    const float* y  = (const float*)d_in[1];
    const float* Wq = (const float*)d_in[2];
    const float* Wk = (const float*)d_in[3];
    const float* Wv = (const float*)d_in[4];
    const float* Wo = (const float*)d_in[5];
    const float* bo = (const float*)d_in[6];
    float* out = (float*)d_out;

#define GET(sym, var) void* var; cudaGetSymbolAddress(&var, sym)
    GET(g_xh, xh); GET(g_yh, yh);
    GET(g_wqh, wqh); GET(g_wkh, wkh); GET(g_wvh, wvh); GET(g_woh, woh);
    GET(g_qh, qh); GET(g_kh, kh); GET(g_vh, vh); GET(g_vth, vth);
    GET(g_ph, ph); GET(g_ch, ch);
    GET(g_spart, spart); GET(g_rinv, rinv);
#undef GET

    cudaFuncSetAttribute((void*)gemm1<2>, cudaFuncAttributeMaxDynamicSharedMemorySize, SMEM_B);
    cudaFuncSetAttribute((void*)gemm1<3>, cudaFuncAttributeMaxDynamicSharedMemorySize, SMEM_B);
    cudaFuncSetAttribute((void*)gemm1<5>, cudaFuncAttributeMaxDynamicSharedMemorySize, SMEM_B);
    cudaFuncSetAttribute((void*)gemm1<6>, cudaFuncAttributeMaxDynamicSharedMemorySize, SMEM_B);

    const int MBN = BATCH * NSEQ;            // 16384

    // f32 -> f16 conversions (batched)
    {
        int n4 = BATCH * NSEQ * DDIM / 4;
        dim3 g1(n4 / 256, 1, 2);
        conv_xy<<<g1, 256>>>((const float4*)x, (f16*)xh,
                             (const float4*)y, (f16*)yh, n4);
        int w4 = EDIM * DDIM / 4;
        dim3 g2(w4 / 256, 1, 4);
        conv_w<<<g2, 256>>>((const float4*)Wq, (f16*)wqh,
                            (const float4*)Wk, (f16*)wkh,
                            (const float4*)Wv, (f16*)wvh,
                            (const float4*)Wo, (f16*)woh, w4);
    }

    // projections (hi-only out): q = y@Wq^T, k = x@Wk^T, v = x@Wv^T
    {
        dim3 grid(EDIM / 256, MBN / 128, 1);
        gemm1<5><<<grid, 256, SMEM_B>>>((f16*)yh, (f16*)wqh, nullptr, (f16*)qh,
                                        nullptr, nullptr, nullptr, MBN, EDIM, DDIM, 0, 0, 0);
        gemm1<5><<<grid, 256, SMEM_B>>>((f16*)xh, (f16*)wkh, nullptr, (f16*)kh,
                                        nullptr, nullptr, nullptr, MBN, EDIM, DDIM, 0, 0, 0);
        gemm1<5><<<grid, 256, SMEM_B>>>((f16*)xh, (f16*)wvh, nullptr, (f16*)vh,
                                        nullptr, nullptr, nullptr, MBN, EDIM, DDIM, 0, 0, 0);
    }

    // scores+exp: E = exp(q@k^T / 32), hi out + row partials (grid.x = 16)
    {
        dim3 grid(NSEQ / 256, NSEQ / 128, BATCH);
        gemm1<3><<<grid, 256, SMEM_B>>>((f16*)qh, (f16*)kh, nullptr, (f16*)ph,
                                        nullptr, (float*)spart, nullptr,
                                        NSEQ, NSEQ, EDIM,
                                        (long long)NSEQ * EDIM, (long long)NSEQ * EDIM,
                                        (long long)NSEQ * NSEQ);
    }

    // rinv = 1/rowsum
    rowsum_inv<<<MBN / 256, 256>>>((const float*)spart, (float*)rinv, MBN);

    // transpose V
    {
        dim3 grid(EDIM / 64, NSEQ / 64, BATCH);
        transpose_k<<<grid, 256>>>((f16*)vh, (f16*)vth);
    }

    // ctx = rinv ⊙ (E @ V), hi-only out
    {
        dim3 grid(EDIM / 256, NSEQ / 128, BATCH);
        gemm1<6><<<grid, 256, SMEM_B>>>((f16*)ph, (f16*)vth, nullptr, (f16*)ch,
                                        nullptr, nullptr, (const float*)rinv,
                                        NSEQ, EDIM, NSEQ,
                                        (long long)NSEQ * NSEQ, (long long)EDIM * NSEQ,
                                        (long long)NSEQ * EDIM);
    }

    // out = ctx @ Wo^T + bo (fp32 out)
    {
        dim3 grid(DDIM / 256, MBN / 128, 1);
        gemm1<2><<<grid, 256, SMEM_B>>>((f16*)ch, (f16*)woh, out, nullptr,
                                        bo, nullptr, nullptr, MBN, DDIM, EDIM, 0, 0, 0);
    }

    (void)in_sizes; (void)n_in; (void)out_size;
}

// round 14
// speedup vs baseline: 2.6911x; 1.1618x over previous
#include <cuda_runtime.h>
#include <cuda_fp16.h>
#include <stdint.h>

#define BATCH 4
#define NSEQ  4096
#define DDIM  1024
#define EDIM  1024

typedef __half f16;

// ---------------- scratch (device globals; no allocations allowed) -------------
__device__ f16 g_xh[(size_t)BATCH*NSEQ*DDIM];
__device__ f16 g_yh[(size_t)BATCH*NSEQ*DDIM];
__device__ f16 g_wqh[(size_t)EDIM*DDIM];
__device__ f16 g_wkh[(size_t)EDIM*DDIM];
__device__ f16 g_wvh[(size_t)EDIM*DDIM];
__device__ f16 g_woh[(size_t)DDIM*EDIM];
__device__ f16 g_qh[(size_t)BATCH*NSEQ*EDIM];
__device__ f16 g_kh[(size_t)BATCH*NSEQ*EDIM];
__device__ f16 g_vh[(size_t)BATCH*NSEQ*EDIM];
__device__ f16 g_vth[(size_t)BATCH*EDIM*NSEQ];
__device__ f16 g_ph[(size_t)BATCH*NSEQ*NSEQ];
__device__ f16 g_ch[(size_t)BATCH*NSEQ*EDIM];
__device__ float g_spart[(size_t)BATCH*NSEQ*16];
__device__ float g_rinv[(size_t)BATCH*NSEQ];

// ---------------- helpers ----------------
__device__ __forceinline__ uint32_t smem_u32(const void* p) {
    uint32_t a;
    asm("{ .reg .u64 t; cvta.to.shared.u64 t, %1; cvt.u32.u64 %0, t; }" : "=r"(a) : "l"(p));
    return a;
}
__device__ __forceinline__ void cpa16(uint32_t dst, const void* src) {
    asm volatile("cp.async.cg.shared.global [%0], [%1], 16;" :: "r"(dst), "l"(src));
}

#define MMA_F32ACC(c, a, b) \
    asm volatile("mma.sync.aligned.m16n8k16.row.col.f32.f16.f16.f32 " \
                 "{%0,%1,%2,%3},{%4,%5,%6,%7},{%8,%9},{%0,%1,%2,%3};\n" \
                 : "+f"(c[0]), "+f"(c[1]), "+f"(c[2]), "+f"(c[3]) \
                 : "r"(a[0]), "r"(a[1]), "r"(a[2]), "r"(a[3]), "r"(b[0]), "r"(b[1]))

#define LDSM4(r, a) \
    asm volatile("ldmatrix.sync.aligned.m8n8.x4.shared.b16 {%0,%1,%2,%3}, [%4];\n" \
                 : "=r"((r)[0]), "=r"((r)[1]), "=r"((r)[2]), "=r"((r)[3]) : "r"(a))
#define LDSM2(r, a) \
    asm volatile("ldmatrix.sync.aligned.m8n8.x2.shared.b16 {%0,%1}, [%2];\n" \
                 : "=r"((r)[0]), "=r"((r)[1]) : "r"(a))

// ---------------- fp32 -> f16 (batched over z) ----------------
__device__ __forceinline__ void to_f16_one(const float4* src, f16* hi, int i)
{
    float4 v = src[i];
    __half2 h01; h01.x = __float2half_rn(v.x); h01.y = __float2half_rn(v.y);
    __half2 h23; h23.x = __float2half_rn(v.z); h23.y = __float2half_rn(v.w);
    reinterpret_cast<__half2*>(hi)[2*i]   = h01;
    reinterpret_cast<__half2*>(hi)[2*i+1] = h23;
}

__global__ void conv_xy(const float4* __restrict__ x, f16* xh,
                        const float4* __restrict__ y, f16* yh, int n4)
{
    int i = blockIdx.x * blockDim.x + threadIdx.x;
    if (i >= n4) return;
    if (blockIdx.z == 0) to_f16_one(x, xh, i);
    else                 to_f16_one(y, yh, i);
}

__global__ void conv_w(const float4* __restrict__ wq, f16* wqh,
                       const float4* __restrict__ wk, f16* wkh,
                       const float4* __restrict__ wv, f16* wvh,
                       const float4* __restrict__ wo, f16* woh, int n4)
{
    int i = blockIdx.x * blockDim.x + threadIdx.x;
    if (i >= n4) return;
    switch (blockIdx.z) {
        case 0: to_f16_one(wq, wqh, i); break;
        case 1: to_f16_one(wk, wkh, i); break;
        case 2: to_f16_one(wv, wvh, i); break;
        default: to_f16_one(wo, woh, i); break;
    }
}

// ---------------- f16 transpose per batch: [NSEQ, EDIM] -> [EDIM, NSEQ] -------
__global__ __launch_bounds__(256)
void transpose_k(const f16* __restrict__ in, f16* __restrict__ out)
{
    __shared__ f16 t[64][72];
    const int z = blockIdx.z;
    in  += (size_t)z * NSEQ * EDIM;
    out += (size_t)z * EDIM * NSEQ;
    const int x0 = blockIdx.x * 64;
    const int y0 = blockIdx.y * 64;
    const int tid = threadIdx.x;
    const int r = tid >> 3, c = (tid & 7) * 8;
#pragma unroll
    for (int i = 0; i < 2; i++) {
        uint4 v = *(const uint4*)(in + (size_t)(y0 + r + 32*i) * EDIM + x0 + c);
        *(uint4*)&t[r + 32*i][c] = v;
    }
    __syncthreads();
#pragma unroll
    for (int i = 0; i < 2; i++) {
        int orow = r + 32*i;
        f16 tmp[8];
#pragma unroll
        for (int j = 0; j < 8; j++) tmp[j] = t[c + j][orow];
        *(uint4*)(out + (size_t)(x0 + orow) * NSEQ + y0 + c) = *(uint4*)tmp;
    }
}

// ---------------- rowsum partials -> 1/sum ----------------
__global__ void rowsum_inv(const float* __restrict__ spart, float* __restrict__ rinv, int nrows)
{
    int r = blockIdx.x * 256 + threadIdx.x;
    if (r >= nrows) return;
    float s = 0.0f;
#pragma unroll
    for (int j = 0; j < 16; j++) s += spart[(size_t)r * 16 + j];
    rinv[r] = 1.0f / s;
}

// ---------------- 1-term f16 HMMA GEMM: C = Ah·Bh^T ---------------------------
// CTA tile 128 (M) x 256 (N), K_TILE=64, 3-stage cp.async, 8 warps (64x64).
// Row layout: 64 f16 = 128 data bytes, padded to 144 (16B-chunk stride 9: conflict-free).
// OUT_MODE: 2 fp32+bias; 3 exp(acc/32) hi + row partials; 5 hi-only;
//           6 acc*rinv[row] hi-only.

#define NSTAGE   3
#define ROW_B    144
#define MAT_A    (128 * ROW_B)
#define MAT_BB   (256 * ROW_B)
#define OFF_B    (MAT_A)
#define STAGE_B  (MAT_A + MAT_BB)            // 55296
#define SMEM_B   (NSTAGE * STAGE_B)          // 165888

template<int OUT_MODE>
__global__ __launch_bounds__(256, 1)
void gemm1(const f16* __restrict__ Ah, const f16* __restrict__ Bh,
           float* __restrict__ outF, f16* __restrict__ outHi,
           const float* __restrict__ bias,
           float* __restrict__ spart, const float* __restrict__ rowscale,
           int M, int N, int K, long long sA, long long sB, long long sC)
{
    extern __shared__ __align__(16) char dsm[];
    __shared__ float part[128][4];
    const uint32_t sb = smem_u32(dsm);

    const int z = blockIdx.z;
    Ah += (size_t)z * sA;
    Bh += (size_t)z * sB;

    const int tid = threadIdx.x;
    const int lane = tid & 31;
    const int warp = tid >> 5;
    const int m0 = blockIdx.y * 128;
    const int n0 = blockIdx.x * 256;

    const int wm0 = (warp & 1) * 64;          // 2 warps along M
    const int wn0 = (warp >> 1) * 64;         // 4 warps along N
    const int arow = lane & 15;
    const int acol = (lane >> 4) * 8;
    const int brow = lane & 7;
    const int bcol = ((lane >> 3) & 1) * 8;

    const int nk = K >> 6;                    // K-tiles of 64

    const int lr = tid >> 3;                  // 0..31
    const int lc = tid & 7;                   // 16B chunk 0..7

    auto load_stage = [&](int kt, int stg) {
        const uint32_t base = sb + stg * STAGE_B;
        const int kk = kt << 6;
        // A: 128 rows x 8 chunks = 1024; 4 per thread
#pragma unroll
        for (int i = 0; i < 4; i++) {
            const int row = lr + 32 * i;
            cpa16(base + row * ROW_B + lc * 16,
                  Ah + (size_t)(m0 + row) * K + kk + lc * 8);
        }
        // B: 256 rows x 8 chunks = 2048; 8 per thread
#pragma unroll
        for (int i = 0; i < 8; i++) {
            const int row = lr + 32 * i;
            cpa16(base + OFF_B + row * ROW_B + lc * 16,
                  Bh + (size_t)(n0 + row) * K + kk + lc * 8);
        }
        asm volatile("cp.async.commit_group;" ::: "memory");
    };

    float acc[4][8][4];
#pragma unroll
    for (int t = 0; t < 4; t++)
#pragma unroll
        for (int u = 0; u < 8; u++)
#pragma unroll
            for (int e = 0; e < 4; e++) acc[t][u][e] = 0.0f;

    load_stage(0, 0);
    if (nk > 1) load_stage(1, 1);

    for (int kt = 0; kt < nk; kt++) {
        if (kt + 1 < nk) asm volatile("cp.async.wait_group 1;" ::: "memory");
        else             asm volatile("cp.async.wait_group 0;" ::: "memory");
        __syncthreads();

        if (kt + 2 < nk) load_stage(kt + 2, (kt + 2) % NSTAGE);

        const uint32_t base = sb + (kt % NSTAGE) * STAGE_B;

#pragma unroll
        for (int ks = 0; ks < 4; ks++) {
            const int kbyte = ks * 32;
            uint32_t ah[4][4], bh[8][2];
#pragma unroll
            for (int t = 0; t < 4; t++) {
                uint32_t ad = base + (uint32_t)(wm0 + t*16 + arow) * ROW_B + kbyte + acol * 2;
                LDSM4(ah[t], ad);
            }
#pragma unroll
            for (int u = 0; u < 8; u++) {
                uint32_t bd = base + OFF_B + (uint32_t)(wn0 + u*8 + brow) * ROW_B + kbyte + bcol * 2;
                LDSM2(bh[u], bd);
            }
#pragma unroll
            for (int t = 0; t < 4; t++)
#pragma unroll
                for (int u = 0; u < 8; u++) MMA_F32ACC(acc[t][u], ah[t], bh[u]);
        }
    }

    // ---- epilogue ----
    const size_t cbase = (size_t)z * sC;
#pragma unroll
    for (int t = 0; t < 4; t++) {
        const int gm = m0 + wm0 + t * 16 + (lane >> 2);
        float rs0 = 0.0f, rs1 = 0.0f;
        float rv0 = 1.0f, rv1 = 1.0f;
        if (OUT_MODE == 6) {
            rv0 = rowscale[(size_t)z * M + gm];
            rv1 = rowscale[(size_t)z * M + gm + 8];
        }
#pragma unroll
        for (int u = 0; u < 8; u++) {
            const int gn = n0 + wn0 + u * 8 + (lane & 3) * 2;
            float v00 = acc[t][u][0], v01 = acc[t][u][1];
            float v10 = acc[t][u][2], v11 = acc[t][u][3];
            if (OUT_MODE == 2) {
                float b0 = bias[gn], b1 = bias[gn + 1];
                v00 += b0; v01 += b1; v10 += b0; v11 += b1;
            }
            if (OUT_MODE == 3) {
                v00 = __expf(v00 * 0.03125f);
                v01 = __expf(v01 * 0.03125f);
                v10 = __expf(v10 * 0.03125f);
                v11 = __expf(v11 * 0.03125f);
                rs0 += v00 + v01;
                rs1 += v10 + v11;
            }
            if (OUT_MODE == 6) {
                v00 *= rv0; v01 *= rv0; v10 *= rv1; v11 *= rv1;
            }
            if (OUT_MODE == 2) {
                *(float2*)(outF + cbase + (size_t)gm * N + gn) = make_float2(v00, v01);
                *(float2*)(outF + cbase + (size_t)(gm + 8) * N + gn) = make_float2(v10, v11);
            } else {
                __half2 hp0; hp0.x = __float2half_rn(v00); hp0.y = __float2half_rn(v01);
                __half2 hp1; hp1.x = __float2half_rn(v10); hp1.y = __float2half_rn(v11);
                *(__half2*)(outHi + cbase + (size_t)gm * N + gn) = hp0;
                *(__half2*)(outHi + cbase + (size_t)(gm + 8) * N + gn) = hp1;
            }
        }
        if (OUT_MODE == 3) {
            rs0 += __shfl_xor_sync(0xffffffffu, rs0, 1);
            rs0 += __shfl_xor_sync(0xffffffffu, rs0, 2);
            rs1 += __shfl_xor_sync(0xffffffffu, rs1, 1);
            rs1 += __shfl_xor_sync(0xffffffffu, rs1, 2);
            if ((lane & 3) == 0) {
                part[wm0 + t * 16 + (lane >> 2)][warp >> 1] = rs0;
                part[wm0 + t * 16 + (lane >> 2) + 8][warp >> 1] = rs1;
            }
        }
    }
    if (OUT_MODE == 3) {
        __syncthreads();
        if (tid < 128) {
            float s = part[tid][0] + part[tid][1] + part[tid][2] + part[tid][3];
            spart[((size_t)z * M + m0 + tid) * 16 + blockIdx.x] = s;
        }
    }
}

// ---------------- host ----------------
extern "C" void kernel_launch(void* const* d_in, const int* in_sizes, int n_in,
                              void* d_out, int out_size)
{
    const float* x  = (const float*)d_in[0];
    const float* y  = (const float*)d_in[1];
    const float* Wq = (const float*)d_in[2];
    const float* Wk = (const float*)d_in[3];
    const float* Wv = (const float*)d_in[4];
    const float* Wo = (const float*)d_in[5];
    const float* bo = (const float*)d_in[6];
    float* out = (float*)d_out;

#define GET(sym, var) void* var; cudaGetSymbolAddress(&var, sym)
    GET(g_xh, xh); GET(g_yh, yh);
    GET(g_wqh, wqh); GET(g_wkh, wkh); GET(g_wvh, wvh); GET(g_woh, woh);
    GET(g_qh, qh); GET(g_kh, kh); GET(g_vh, vh); GET(g_vth, vth);
    GET(g_ph, ph); GET(g_ch, ch);
    GET(g_spart, spart); GET(g_rinv, rinv);
#undef GET

    cudaFuncSetAttribute((void*)gemm1<2>, cudaFuncAttributeMaxDynamicSharedMemorySize, SMEM_B);
    cudaFuncSetAttribute((void*)gemm1<3>, cudaFuncAttributeMaxDynamicSharedMemorySize, SMEM_B);
    cudaFuncSetAttribute((void*)gemm1<5>, cudaFuncAttributeMaxDynamicSharedMemorySize, SMEM_B);
    cudaFuncSetAttribute((void*)gemm1<6>, cudaFuncAttributeMaxDynamicSharedMemorySize, SMEM_B);

    const int MBN = BATCH * NSEQ;            // 16384

    // f32 -> f16 conversions (batched)
    {
        int n4 = BATCH * NSEQ * DDIM / 4;
        dim3 g1(n4 / 256, 1, 2);
        conv_xy<<<g1, 256>>>((const float4*)x, (f16*)xh,
                             (const float4*)y, (f16*)yh, n4);
        int w4 = EDIM * DDIM / 4;
        dim3 g2(w4 / 256, 1, 4);
        conv_w<<<g2, 256>>>((const float4*)Wq, (f16*)wqh,
                            (const float4*)Wk, (f16*)wkh,
                            (const float4*)Wv, (f16*)wvh,
                            (const float4*)Wo, (f16*)woh, w4);
    }

    // projections (hi-only out): q = y@Wq^T, k = x@Wk^T, v = x@Wv^T
    {
        dim3 grid(EDIM / 256, MBN / 128, 1);
        gemm1<5><<<grid, 256, SMEM_B>>>((f16*)yh, (f16*)wqh, nullptr, (f16*)qh,
                                        nullptr, nullptr, nullptr, MBN, EDIM, DDIM, 0, 0, 0);
        gemm1<5><<<grid, 256, SMEM_B>>>((f16*)xh, (f16*)wkh, nullptr, (f16*)kh,
                                        nullptr, nullptr, nullptr, MBN, EDIM, DDIM, 0, 0, 0);
        gemm1<5><<<grid, 256, SMEM_B>>>((f16*)xh, (f16*)wvh, nullptr, (f16*)vh,
                                        nullptr, nullptr, nullptr, MBN, EDIM, DDIM, 0, 0, 0);
    }

    // scores+exp: E = exp(q@k^T / 32), hi out + row partials (grid.x = 16)
    {
        dim3 grid(NSEQ / 256, NSEQ / 128, BATCH);
        gemm1<3><<<grid, 256, SMEM_B>>>((f16*)qh, (f16*)kh, nullptr, (f16*)ph,
                                        nullptr, (float*)spart, nullptr,
                                        NSEQ, NSEQ, EDIM,
                                        (long long)NSEQ * EDIM, (long long)NSEQ * EDIM,
                                        (long long)NSEQ * NSEQ);
    }

    // rinv = 1/rowsum
    rowsum_inv<<<MBN / 256, 256>>>((const float*)spart, (float*)rinv, MBN);

    // transpose V
    {
        dim3 grid(EDIM / 64, NSEQ / 64, BATCH);
        transpose_k<<<grid, 256>>>((f16*)vh, (f16*)vth);
    }

    // ctx = rinv ⊙ (E @ V), hi-only out
    {
        dim3 grid(EDIM / 256, NSEQ / 128, BATCH);
        gemm1<6><<<grid, 256, SMEM_B>>>((f16*)ph, (f16*)vth, nullptr, (f16*)ch,
                                        nullptr, nullptr, (const float*)rinv,
                                        NSEQ, EDIM, NSEQ,
                                        (long long)NSEQ * NSEQ, (long long)EDIM * NSEQ,
                                        (long long)NSEQ * EDIM);
    }

    // out = ctx @ Wo^T + bo (fp32 out)
    {
        dim3 grid(DDIM / 256, MBN / 128, 1);
        gemm1<2><<<grid, 256, SMEM_B>>>((f16*)ch, (f16*)woh, out, nullptr,
                                        bo, nullptr, nullptr, MBN, DDIM, EDIM, 0, 0, 0);
    }

    (void)in_sizes; (void)n_in; (void)out_size;
}

// round 16
// speedup vs baseline: 2.8149x; 1.0460x over previous
#include <cuda_runtime.h>
#include <cuda_fp16.h>
#include <stdint.h>

#define BATCH 4
#define NSEQ  4096
#define DDIM  1024
#define EDIM  1024

typedef __half f16;

// ---------------- scratch (device globals; no allocations allowed) -------------
__device__ f16 g_xh[(size_t)BATCH*NSEQ*DDIM];
__device__ f16 g_yh[(size_t)BATCH*NSEQ*DDIM];
__device__ f16 g_wqh[(size_t)EDIM*DDIM];
__device__ f16 g_wkh[(size_t)EDIM*DDIM];
__device__ f16 g_wvh[(size_t)EDIM*DDIM];
__device__ f16 g_woh[(size_t)DDIM*EDIM];
__device__ f16 g_qh[(size_t)BATCH*NSEQ*EDIM];
__device__ f16 g_kh[(size_t)BATCH*NSEQ*EDIM];
__device__ f16 g_vh[(size_t)BATCH*NSEQ*EDIM];
__device__ f16 g_vth[(size_t)BATCH*EDIM*NSEQ];
__device__ f16 g_ph[(size_t)BATCH*NSEQ*NSEQ];
__device__ f16 g_ch[(size_t)BATCH*NSEQ*EDIM];
__device__ float g_spart[(size_t)BATCH*NSEQ*16];
__device__ float g_rinv[(size_t)BATCH*NSEQ];

// ---------------- helpers ----------------
__device__ __forceinline__ uint32_t smem_u32(const void* p) {
    uint32_t a;
    asm("{ .reg .u64 t; cvta.to.shared.u64 t, %1; cvt.u32.u64 %0, t; }" : "=r"(a) : "l"(p));
    return a;
}
__device__ __forceinline__ void cpa16(uint32_t dst, const void* src) {
    asm volatile("cp.async.cg.shared.global [%0], [%1], 16;" :: "r"(dst), "l"(src));
}

#define MMA_F32ACC(c, a, b) \
    asm volatile("mma.sync.aligned.m16n8k16.row.col.f32.f16.f16.f32 " \
                 "{%0,%1,%2,%3},{%4,%5,%6,%7},{%8,%9},{%0,%1,%2,%3};\n" \
                 : "+f"(c[0]), "+f"(c[1]), "+f"(c[2]), "+f"(c[3]) \
                 : "r"(a[0]), "r"(a[1]), "r"(a[2]), "r"(a[3]), "r"(b[0]), "r"(b[1]))

#define LDSM4(r, a) \
    asm volatile("ldmatrix.sync.aligned.m8n8.x4.shared.b16 {%0,%1,%2,%3}, [%4];\n" \
                 : "=r"((r)[0]), "=r"((r)[1]), "=r"((r)[2]), "=r"((r)[3]) : "r"(a))
#define LDSM2(r, a) \
    asm volatile("ldmatrix.sync.aligned.m8n8.x2.shared.b16 {%0,%1}, [%2];\n" \
                 : "=r"((r)[0]), "=r"((r)[1]) : "r"(a))

// ---------------- fp32 -> f16 (batched over z) ----------------
__device__ __forceinline__ void to_f16_one(const float4* src, f16* hi, int i)
{
    float4 v = src[i];
    __half2 h01; h01.x = __float2half_rn(v.x); h01.y = __float2half_rn(v.y);
    __half2 h23; h23.x = __float2half_rn(v.z); h23.y = __float2half_rn(v.w);
    reinterpret_cast<__half2*>(hi)[2*i]   = h01;
    reinterpret_cast<__half2*>(hi)[2*i+1] = h23;
}

__global__ void conv_xy(const float4* __restrict__ x, f16* xh,
                        const float4* __restrict__ y, f16* yh, int n4)
{
    int i = blockIdx.x * blockDim.x + threadIdx.x;
    if (i >= n4) return;
    if (blockIdx.z == 0) to_f16_one(x, xh, i);
    else                 to_f16_one(y, yh, i);
}

__global__ void conv_w(const float4* __restrict__ wq, f16* wqh,
                       const float4* __restrict__ wk, f16* wkh,
                       const float4* __restrict__ wv, f16* wvh,
                       const float4* __restrict__ wo, f16* woh, int n4)
{
    int i = blockIdx.x * blockDim.x + threadIdx.x;
    if (i >= n4) return;
    switch (blockIdx.z) {
        case 0: to_f16_one(wq, wqh, i); break;
        case 1: to_f16_one(wk, wkh, i); break;
        case 2: to_f16_one(wv, wvh, i); break;
        default: to_f16_one(wo, woh, i); break;
    }
}

// ---------------- f16 transpose per batch: [NSEQ, EDIM] -> [EDIM, NSEQ] -------
__global__ __launch_bounds__(256)
void transpose_k(const f16* __restrict__ in, f16* __restrict__ out)
{
    __shared__ f16 t[64][72];
    const int z = blockIdx.z;
    in  += (size_t)z * NSEQ * EDIM;
    out += (size_t)z * EDIM * NSEQ;
    const int x0 = blockIdx.x * 64;
    const int y0 = blockIdx.y * 64;
    const int tid = threadIdx.x;
    const int r = tid >> 3, c = (tid & 7) * 8;
#pragma unroll
    for (int i = 0; i < 2; i++) {
        uint4 v = *(const uint4*)(in + (size_t)(y0 + r + 32*i) * EDIM + x0 + c);
        *(uint4*)&t[r + 32*i][c] = v;
    }
    __syncthreads();
#pragma unroll
    for (int i = 0; i < 2; i++) {
        int orow = r + 32*i;
        f16 tmp[8];
#pragma unroll
        for (int j = 0; j < 8; j++) tmp[j] = t[c + j][orow];
        *(uint4*)(out + (size_t)(x0 + orow) * NSEQ + y0 + c) = *(uint4*)tmp;
    }
}

// ---------------- rowsum partials -> 1/sum ----------------
__global__ void rowsum_inv(const float* __restrict__ spart, float* __restrict__ rinv, int nrows)
{
    int r = blockIdx.x * 256 + threadIdx.x;
    if (r >= nrows) return;
    float s = 0.0f;
#pragma unroll
    for (int j = 0; j < 16; j++) s += spart[(size_t)r * 16 + j];
    rinv[r] = 1.0f / s;
}

// ---------------- 1-term f16 HMMA GEMM: C = Ah·Bh^T ---------------------------
// CTA tile 128 (M) x 256 (N), K_TILE=128, 2-stage cp.async, 8 warps (64x64).
// Race-free 2-stage schedule: load(kt+2) issued only AFTER compute(kt) drains
// (second __syncthreads), so it overlaps compute(kt+1) on the other stage.
// Row layout: 128 f16 = 256 data bytes, padded to 272 (17x16B: conflict-free).
// OUT_MODE: 2 fp32+bias; 3 exp(acc/32) hi + row partials; 5 hi-only;
//           6 acc*rinv[row] hi-only.

#define ROW_B    272
#define MAT_A    (128 * ROW_B)
#define MAT_BB   (256 * ROW_B)
#define OFF_B    (MAT_A)
#define STAGE_B  (MAT_A + MAT_BB)            // 104448
#define SMEM_B   (2 * STAGE_B)               // 208896

template<int OUT_MODE>
__global__ __launch_bounds__(256, 1)
void gemm1(const f16* __restrict__ Ah, const f16* __restrict__ Bh,
           float* __restrict__ outF, f16* __restrict__ outHi,
           const float* __restrict__ bias,
           float* __restrict__ spart, const float* __restrict__ rowscale,
           int M, int N, int K, long long sA, long long sB, long long sC)
{
    extern __shared__ __align__(16) char dsm[];
    __shared__ float part[128][4];
    const uint32_t sb = smem_u32(dsm);

    const int z = blockIdx.z;
    Ah += (size_t)z * sA;
    Bh += (size_t)z * sB;

    const int tid = threadIdx.x;
    const int lane = tid & 31;
    const int warp = tid >> 5;
    const int m0 = blockIdx.y * 128;
    const int n0 = blockIdx.x * 256;

    const int wm0 = (warp & 1) * 64;          // 2 warps along M
    const int wn0 = (warp >> 1) * 64;         // 4 warps along N
    const int arow = lane & 15;
    const int acol = (lane >> 4) * 8;
    const int brow = lane & 7;
    const int bcol = ((lane >> 3) & 1) * 8;

    const int nk = K >> 7;                    // K-tiles of 128

    const int lr = tid >> 4;                  // 0..15
    const int lc = tid & 15;                  // 16B chunk 0..15

    auto load_stage = [&](int kt, int stg) {
        const uint32_t base = sb + stg * STAGE_B;
        const int kk = kt << 7;
#pragma unroll
        for (int i = 0; i < 8; i++) {
            const int row = lr + 16 * i;
            cpa16(base + row * ROW_B + lc * 16,
                  Ah + (size_t)(m0 + row) * K + kk + lc * 8);
        }
#pragma unroll
        for (int i = 0; i < 16; i++) {
            const int row = lr + 16 * i;
            cpa16(base + OFF_B + row * ROW_B + lc * 16,
                  Bh + (size_t)(n0 + row) * K + kk + lc * 8);
        }
        asm volatile("cp.async.commit_group;" ::: "memory");
    };

    float acc[4][8][4];
#pragma unroll
    for (int t = 0; t < 4; t++)
#pragma unroll
        for (int u = 0; u < 8; u++)
#pragma unroll
            for (int e = 0; e < 4; e++) acc[t][u][e] = 0.0f;

    load_stage(0, 0);
    if (nk > 1) load_stage(1, 1);

    for (int kt = 0; kt < nk; kt++) {
        if (kt + 1 < nk) asm volatile("cp.async.wait_group 1;" ::: "memory");
        else             asm volatile("cp.async.wait_group 0;" ::: "memory");
        __syncthreads();

        const uint32_t base = sb + (kt & 1) * STAGE_B;

#pragma unroll
        for (int ks = 0; ks < 8; ks++) {
            const int kbyte = ks * 32;
            uint32_t ah[4][4], bh[8][2];
#pragma unroll
            for (int t = 0; t < 4; t++) {
                uint32_t ad = base + (uint32_t)(wm0 + t*16 + arow) * ROW_B + kbyte + acol * 2;
                LDSM4(ah[t], ad);
            }
#pragma unroll
            for (int u = 0; u < 8; u++) {
                uint32_t bd = base + OFF_B + (uint32_t)(wn0 + u*8 + brow) * ROW_B + kbyte + bcol * 2;
                LDSM2(bh[u], bd);
            }
#pragma unroll
            for (int t = 0; t < 4; t++)
#pragma unroll
                for (int u = 0; u < 8; u++) MMA_F32ACC(acc[t][u], ah[t], bh[u]);
        }

        // drain reads of this stage, THEN reuse it for kt+2 (overlaps kt+1 compute)
        if (kt + 2 < nk) {
            __syncthreads();
            load_stage(kt + 2, kt & 1);
        }
    }

    // ---- epilogue ----
    const size_t cbase = (size_t)z * sC;
#pragma unroll
    for (int t = 0; t < 4; t++) {
        const int gm = m0 + wm0 + t * 16 + (lane >> 2);
        float rs0 = 0.0f, rs1 = 0.0f;
        float rv0 = 1.0f, rv1 = 1.0f;
        if (OUT_MODE == 6) {
            rv0 = rowscale[(size_t)z * M + gm];
            rv1 = rowscale[(size_t)z * M + gm + 8];
        }
#pragma unroll
        for (int u = 0; u < 8; u++) {
            const int gn = n0 + wn0 + u * 8 + (lane & 3) * 2;
            float v00 = acc[t][u][0], v01 = acc[t][u][1];
            float v10 = acc[t][u][2], v11 = acc[t][u][3];
            if (OUT_MODE == 2) {
                float b0 = bias[gn], b1 = bias[gn + 1];
                v00 += b0; v01 += b1; v10 += b0; v11 += b1;
            }
            if (OUT_MODE == 3) {
                v00 = __expf(v00 * 0.03125f);
                v01 = __expf(v01 * 0.03125f);
                v10 = __expf(v10 * 0.03125f);
                v11 = __expf(v11 * 0.03125f);
                rs0 += v00 + v01;
                rs1 += v10 + v11;
            }
            if (OUT_MODE == 6) {
                v00 *= rv0; v01 *= rv0; v10 *= rv1; v11 *= rv1;
            }
            if (OUT_MODE == 2) {
                *(float2*)(outF + cbase + (size_t)gm * N + gn) = make_float2(v00, v01);
                *(float2*)(outF + cbase + (size_t)(gm + 8) * N + gn) = make_float2(v10, v11);
            } else {
                __half2 hp0; hp0.x = __float2half_rn(v00); hp0.y = __float2half_rn(v01);
                __half2 hp1; hp1.x = __float2half_rn(v10); hp1.y = __float2half_rn(v11);
                *(__half2*)(outHi + cbase + (size_t)gm * N + gn) = hp0;
                *(__half2*)(outHi + cbase + (size_t)(gm + 8) * N + gn) = hp1;
            }
        }
        if (OUT_MODE == 3) {
            rs0 += __shfl_xor_sync(0xffffffffu, rs0, 1);
            rs0 += __shfl_xor_sync(0xffffffffu, rs0, 2);
            rs1 += __shfl_xor_sync(0xffffffffu, rs1, 1);
            rs1 += __shfl_xor_sync(0xffffffffu, rs1, 2);
            if ((lane & 3) == 0) {
                part[wm0 + t * 16 + (lane >> 2)][warp >> 1] = rs0;
                part[wm0 + t * 16 + (lane >> 2) + 8][warp >> 1] = rs1;
            }
        }
    }
    if (OUT_MODE == 3) {
        __syncthreads();
        if (tid < 128) {
            float s = part[tid][0] + part[tid][1] + part[tid][2] + part[tid][3];
            spart[((size_t)z * M + m0 + tid) * 16 + blockIdx.x] = s;
        }
    }
}

// ---------------- host ----------------
extern "C" void kernel_launch(void* const* d_in, const int* in_sizes, int n_in,
                              void* d_out, int out_size)
{
    const float* x  = (const float*)d_in[0];
    const float* y  = (const float*)d_in[1];
    const float* Wq = (const float*)d_in[2];
    const float* Wk = (const float*)d_in[3];
    const float* Wv = (const float*)d_in[4];
    const float* Wo = (const float*)d_in[5];
    const float* bo = (const float*)d_in[6];
    float* out = (float*)d_out;

#define GET(sym, var) void* var; cudaGetSymbolAddress(&var, sym)
    GET(g_xh, xh); GET(g_yh, yh);
    GET(g_wqh, wqh); GET(g_wkh, wkh); GET(g_wvh, wvh); GET(g_woh, woh);
    GET(g_qh, qh); GET(g_kh, kh); GET(g_vh, vh); GET(g_vth, vth);
    GET(g_ph, ph); GET(g_ch, ch);
    GET(g_spart, spart); GET(g_rinv, rinv);
#undef GET

    cudaFuncSetAttribute((void*)gemm1<2>, cudaFuncAttributeMaxDynamicSharedMemorySize, SMEM_B);
    cudaFuncSetAttribute((void*)gemm1<3>, cudaFuncAttributeMaxDynamicSharedMemorySize, SMEM_B);
    cudaFuncSetAttribute((void*)gemm1<5>, cudaFuncAttributeMaxDynamicSharedMemorySize, SMEM_B);
    cudaFuncSetAttribute((void*)gemm1<6>, cudaFuncAttributeMaxDynamicSharedMemorySize, SMEM_B);

    const int MBN = BATCH * NSEQ;            // 16384

    // f32 -> f16 conversions (batched)
    {
        int n4 = BATCH * NSEQ * DDIM / 4;
        dim3 g1(n4 / 256, 1, 2);
        conv_xy<<<g1, 256>>>((const float4*)x, (f16*)xh,
                             (const float4*)y, (f16*)yh, n4);
        int w4 = EDIM * DDIM / 4;
        dim3 g2(w4 / 256, 1, 4);
        conv_w<<<g2, 256>>>((const float4*)Wq, (f16*)wqh,
                            (const float4*)Wk, (f16*)wkh,
                            (const float4*)Wv, (f16*)wvh,
                            (const float4*)Wo, (f16*)woh, w4);
    }

    // projections (hi-only out): q = y@Wq^T, k = x@Wk^T, v = x@Wv^T
    {
        dim3 grid(EDIM / 256, MBN / 128, 1);
        gemm1<5><<<grid, 256, SMEM_B>>>((f16*)yh, (f16*)wqh, nullptr, (f16*)qh,
                                        nullptr, nullptr, nullptr, MBN, EDIM, DDIM, 0, 0, 0);
        gemm1<5><<<grid, 256, SMEM_B>>>((f16*)xh, (f16*)wkh, nullptr, (f16*)kh,
                                        nullptr, nullptr, nullptr, MBN, EDIM, DDIM, 0, 0, 0);
        gemm1<5><<<grid, 256, SMEM_B>>>((f16*)xh, (f16*)wvh, nullptr, (f16*)vh,
                                        nullptr, nullptr, nullptr, MBN, EDIM, DDIM, 0, 0, 0);
    }

    // scores+exp: E = exp(q@k^T / 32), hi out + row partials (grid.x = 16)
    {
        dim3 grid(NSEQ / 256, NSEQ / 128, BATCH);
        gemm1<3><<<grid, 256, SMEM_B>>>((f16*)qh, (f16*)kh, nullptr, (f16*)ph,
                                        nullptr, (float*)spart, nullptr,
                                        NSEQ, NSEQ, EDIM,
                                        (long long)NSEQ * EDIM, (long long)NSEQ * EDIM,
                                        (long long)NSEQ * NSEQ);
    }

    // rinv = 1/rowsum
    rowsum_inv<<<MBN / 256, 256>>>((const float*)spart, (float*)rinv, MBN);

    // transpose V
    {
        dim3 grid(EDIM / 64, NSEQ / 64, BATCH);
        transpose_k<<<grid, 256>>>((f16*)vh, (f16*)vth);
    }

    // ctx = rinv ⊙ (E @ V), hi-only out
    {
        dim3 grid(EDIM / 256, NSEQ / 128, BATCH);
        gemm1<6><<<grid, 256, SMEM_B>>>((f16*)ph, (f16*)vth, nullptr, (f16*)ch,
                                        nullptr, nullptr, (const float*)rinv,
                                        NSEQ, EDIM, NSEQ,
                                        (long long)NSEQ * NSEQ, (long long)EDIM * NSEQ,
                                        (long long)NSEQ * EDIM);
    }

    // out = ctx @ Wo^T + bo (fp32 out)
    {
        dim3 grid(DDIM / 256, MBN / 128, 1);
        gemm1<2><<<grid, 256, SMEM_B>>>((f16*)ch, (f16*)woh, out, nullptr,
                                        bo, nullptr, nullptr, MBN, DDIM, EDIM, 0, 0, 0);
    }

    (void)in_sizes; (void)n_in; (void)out_size;
}

// round 17
// speedup vs baseline: 2.8932x; 1.0278x over previous
#include <cuda_runtime.h>
#include <cuda_fp16.h>
#include <stdint.h>

#define BATCH 4
#define NSEQ  4096
#define DDIM  1024
#define EDIM  1024

typedef __half f16;

// ---------------- scratch (device globals; no allocations allowed) -------------
__device__ f16 g_xh[(size_t)BATCH*NSEQ*DDIM];
__device__ f16 g_yh[(size_t)BATCH*NSEQ*DDIM];
__device__ f16 g_wqh[(size_t)EDIM*DDIM];
__device__ f16 g_wkh[(size_t)EDIM*DDIM];
__device__ f16 g_wvh[(size_t)EDIM*DDIM];
__device__ f16 g_woh[(size_t)DDIM*EDIM];
__device__ f16 g_qh[(size_t)BATCH*NSEQ*EDIM];
__device__ f16 g_kh[(size_t)BATCH*NSEQ*EDIM];
__device__ f16 g_vh[(size_t)BATCH*NSEQ*EDIM];
__device__ f16 g_vth[(size_t)BATCH*EDIM*NSEQ];
__device__ f16 g_ph[(size_t)BATCH*NSEQ*NSEQ];
__device__ f16 g_ch[(size_t)BATCH*NSEQ*EDIM];
__device__ float g_spart[(size_t)BATCH*NSEQ*16];
__device__ float g_rinv[(size_t)BATCH*NSEQ];

// ---------------- helpers ----------------
__device__ __forceinline__ uint32_t smem_u32(const void* p) {
    uint32_t a;
    asm("{ .reg .u64 t; cvta.to.shared.u64 t, %1; cvt.u32.u64 %0, t; }" : "=r"(a) : "l"(p));
    return a;
}
__device__ __forceinline__ void cpa16(uint32_t dst, const void* src) {
    asm volatile("cp.async.cg.shared.global [%0], [%1], 16;" :: "r"(dst), "l"(src));
}

#define MMA_F32ACC(c, a, b) \
    asm volatile("mma.sync.aligned.m16n8k16.row.col.f32.f16.f16.f32 " \
                 "{%0,%1,%2,%3},{%4,%5,%6,%7},{%8,%9},{%0,%1,%2,%3};\n" \
                 : "+f"(c[0]), "+f"(c[1]), "+f"(c[2]), "+f"(c[3]) \
                 : "r"(a[0]), "r"(a[1]), "r"(a[2]), "r"(a[3]), "r"(b[0]), "r"(b[1]))

#define LDSM4(r, a) \
    asm volatile("ldmatrix.sync.aligned.m8n8.x4.shared.b16 {%0,%1,%2,%3}, [%4];\n" \
                 : "=r"((r)[0]), "=r"((r)[1]), "=r"((r)[2]), "=r"((r)[3]) : "r"(a))

// ---------------- fp32 -> f16 (batched over z) ----------------
__device__ __forceinline__ void to_f16_one(const float4* src, f16* hi, int i)
{
    float4 v = src[i];
    __half2 h01; h01.x = __float2half_rn(v.x); h01.y = __float2half_rn(v.y);
    __half2 h23; h23.x = __float2half_rn(v.z); h23.y = __float2half_rn(v.w);
    reinterpret_cast<__half2*>(hi)[2*i]   = h01;
    reinterpret_cast<__half2*>(hi)[2*i+1] = h23;
}

__global__ void conv_xy(const float4* __restrict__ x, f16* xh,
                        const float4* __restrict__ y, f16* yh, int n4)
{
    int i = blockIdx.x * blockDim.x + threadIdx.x;
    if (i >= n4) return;
    if (blockIdx.z == 0) to_f16_one(x, xh, i);
    else                 to_f16_one(y, yh, i);
}

__global__ void conv_w(const float4* __restrict__ wq, f16* wqh,
                       const float4* __restrict__ wk, f16* wkh,
                       const float4* __restrict__ wv, f16* wvh,
                       const float4* __restrict__ wo, f16* woh, int n4)
{
    int i = blockIdx.x * blockDim.x + threadIdx.x;
    if (i >= n4) return;
    switch (blockIdx.z) {
        case 0: to_f16_one(wq, wqh, i); break;
        case 1: to_f16_one(wk, wkh, i); break;
        case 2: to_f16_one(wv, wvh, i); break;
        default: to_f16_one(wo, woh, i); break;
    }
}

// ---------------- f16 transpose per batch: [NSEQ, EDIM] -> [EDIM, NSEQ] -------
__global__ __launch_bounds__(256)
void transpose_k(const f16* __restrict__ in, f16* __restrict__ out)
{
    __shared__ f16 t[64][72];
    const int z = blockIdx.z;
    in  += (size_t)z * NSEQ * EDIM;
    out += (size_t)z * EDIM * NSEQ;
    const int x0 = blockIdx.x * 64;
    const int y0 = blockIdx.y * 64;
    const int tid = threadIdx.x;
    const int r = tid >> 3, c = (tid & 7) * 8;
#pragma unroll
    for (int i = 0; i < 2; i++) {
        uint4 v = *(const uint4*)(in + (size_t)(y0 + r + 32*i) * EDIM + x0 + c);
        *(uint4*)&t[r + 32*i][c] = v;
    }
    __syncthreads();
#pragma unroll
    for (int i = 0; i < 2; i++) {
        int orow = r + 32*i;
        f16 tmp[8];
#pragma unroll
        for (int j = 0; j < 8; j++) tmp[j] = t[c + j][orow];
        *(uint4*)(out + (size_t)(x0 + orow) * NSEQ + y0 + c) = *(uint4*)tmp;
    }
}

// ---------------- rowsum partials -> 1/sum ----------------
__global__ void rowsum_inv(const float* __restrict__ spart, float* __restrict__ rinv, int nrows)
{
    int r = blockIdx.x * 256 + threadIdx.x;
    if (r >= nrows) return;
    float s = 0.0f;
#pragma unroll
    for (int j = 0; j < 16; j++) s += spart[(size_t)r * 16 + j];
    rinv[r] = 1.0f / s;
}

// ---------------- shared GEMM machinery -----------------------------------
// CTA tile 128 (M) x 256 (N), K_TILE=128, 2-stage cp.async, 8 warps (64x64).
// Race-free 2-stage: load(kt+2) only after compute(kt) drains (2nd sync).
// Row 128 f16 = 256 data bytes padded to 272 (17x16B: conflict-free).

#define ROW_B    272
#define MAT_A    (128 * ROW_B)
#define MAT_BB   (256 * ROW_B)
#define OFF_B    (MAT_A)
#define STAGE_B  (MAT_A + MAT_BB)            // 104448
#define SMEM_B   (2 * STAGE_B)               // 208896

struct GemmCtx {
    uint32_t sb;
    int tid, lane, warp, m0, n0, wm0, wn0;
    int arow, acol, brow, bcolb, bu;         // bu: u-offset from lane>>4
    int lr, lc;
};

__device__ __forceinline__ void gemm_mainloop(
    const f16* __restrict__ Ah, const f16* __restrict__ Bh,
    int K, const GemmCtx& cx, float acc[4][8][4])
{
    const int nk = K >> 7;
    auto load_stage = [&](int kt, int stg) {
        const uint32_t base = cx.sb + stg * STAGE_B;
        const int kk = kt << 7;
#pragma unroll
        for (int i = 0; i < 8; i++) {
            const int row = cx.lr + 16 * i;
            cpa16(base + row * ROW_B + cx.lc * 16,
                  Ah + (size_t)(cx.m0 + row) * K + kk + cx.lc * 8);
        }
#pragma unroll
        for (int i = 0; i < 16; i++) {
            const int row = cx.lr + 16 * i;
            cpa16(base + OFF_B + row * ROW_B + cx.lc * 16,
                  Bh + (size_t)(cx.n0 + row) * K + kk + cx.lc * 8);
        }
        asm volatile("cp.async.commit_group;" ::: "memory");
    };

    load_stage(0, 0);
    if (nk > 1) load_stage(1, 1);

    for (int kt = 0; kt < nk; kt++) {
        if (kt + 1 < nk) asm volatile("cp.async.wait_group 1;" ::: "memory");
        else             asm volatile("cp.async.wait_group 0;" ::: "memory");
        __syncthreads();

        const uint32_t base = cx.sb + (kt & 1) * STAGE_B;

#pragma unroll
        for (int ks = 0; ks < 8; ks++) {
            const int kbyte = ks * 32;
            uint32_t ah[4][4], bh[4][4];     // bh[p] holds fragments for u=2p, 2p+1
#pragma unroll
            for (int t = 0; t < 4; t++) {
                uint32_t ad = base + (uint32_t)(cx.wm0 + t*16 + cx.arow) * ROW_B + kbyte + cx.acol * 2;
                LDSM4(ah[t], ad);
            }
#pragma unroll
            for (int p = 0; p < 4; p++) {
                // x4: lanes 0-15 -> u=2p (both k-halves), lanes 16-31 -> u=2p+1
                uint32_t bd = base + OFF_B
                            + (uint32_t)(cx.wn0 + (2*p + cx.bu)*8 + cx.brow) * ROW_B
                            + kbyte + cx.bcolb;
                LDSM4(bh[p], bd);
            }
#pragma unroll
            for (int t = 0; t < 4; t++)
#pragma unroll
                for (int p = 0; p < 4; p++) {
                    MMA_F32ACC(acc[t][2*p],   ah[t], (&bh[p][0]));
                    MMA_F32ACC(acc[t][2*p+1], ah[t], (&bh[p][2]));
                }
        }

        if (kt + 2 < nk) {
            __syncthreads();
            load_stage(kt + 2, kt & 1);
        }
    }
}

__device__ __forceinline__ GemmCtx make_ctx(uint32_t sb, int n0blk)
{
    GemmCtx cx;
    cx.sb = sb;
    cx.tid = threadIdx.x;
    cx.lane = cx.tid & 31;
    cx.warp = cx.tid >> 5;
    cx.m0 = blockIdx.y * 128;
    cx.n0 = n0blk * 256;
    cx.wm0 = (cx.warp & 1) * 64;
    cx.wn0 = (cx.warp >> 1) * 64;
    cx.arow = cx.lane & 15;
    cx.acol = (cx.lane >> 4) * 8;
    cx.brow = cx.lane & 7;
    cx.bcolb = ((cx.lane >> 3) & 1) * 16;
    cx.bu = cx.lane >> 4;
    cx.lr = cx.tid >> 4;
    cx.lc = cx.tid & 15;
    return cx;
}

// ---------------- fused 3-projection GEMM (hi-only out) -----------------------
__global__ __launch_bounds__(256, 1)
void gemm_proj(const f16* __restrict__ xh, const f16* __restrict__ yh,
               const f16* __restrict__ wq, const f16* __restrict__ wk,
               const f16* __restrict__ wv,
               f16* __restrict__ q, f16* __restrict__ k, f16* __restrict__ v,
               int M, int N, int K)
{
    extern __shared__ __align__(16) char dsm[];
    const int z = blockIdx.z;
    const f16* Ah = (z == 0) ? yh : xh;
    const f16* Bh = (z == 0) ? wq : (z == 1) ? wk : wv;
    f16* outHi    = (z == 0) ? q  : (z == 1) ? k  : v;

    GemmCtx cx = make_ctx(smem_u32(dsm), blockIdx.x);

    float acc[4][8][4];
#pragma unroll
    for (int t = 0; t < 4; t++)
#pragma unroll
        for (int u = 0; u < 8; u++)
#pragma unroll
            for (int e = 0; e < 4; e++) acc[t][u][e] = 0.0f;

    gemm_mainloop(Ah, Bh, K, cx, acc);

#pragma unroll
    for (int t = 0; t < 4; t++) {
        const int gm = cx.m0 + cx.wm0 + t * 16 + (cx.lane >> 2);
#pragma unroll
        for (int u = 0; u < 8; u++) {
            const int gn = cx.n0 + cx.wn0 + u * 8 + (cx.lane & 3) * 2;
            __half2 hp0; hp0.x = __float2half_rn(acc[t][u][0]); hp0.y = __float2half_rn(acc[t][u][1]);
            __half2 hp1; hp1.x = __float2half_rn(acc[t][u][2]); hp1.y = __float2half_rn(acc[t][u][3]);
            *(__half2*)(outHi + (size_t)gm * N + gn) = hp0;
            *(__half2*)(outHi + (size_t)(gm + 8) * N + gn) = hp1;
        }
    }
}

// ---------------- generic GEMM (modes 2 / 3 / 6) ------------------------------
// OUT_MODE: 2 fp32+bias; 3 exp(acc/32) hi + row partials; 6 acc*rinv[row] hi.
template<int OUT_MODE>
__global__ __launch_bounds__(256, 1)
void gemm1(const f16* __restrict__ Ah, const f16* __restrict__ Bh,
           float* __restrict__ outF, f16* __restrict__ outHi,
           const float* __restrict__ bias,
           float* __restrict__ spart, const float* __restrict__ rowscale,
           int M, int N, int K, long long sA, long long sB, long long sC)
{
    extern __shared__ __align__(16) char dsm[];
    __shared__ float part[128][4];

    const int z = blockIdx.z;
    Ah += (size_t)z * sA;
    Bh += (size_t)z * sB;

    GemmCtx cx = make_ctx(smem_u32(dsm), blockIdx.x);

    float acc[4][8][4];
#pragma unroll
    for (int t = 0; t < 4; t++)
#pragma unroll
        for (int u = 0; u < 8; u++)
#pragma unroll
            for (int e = 0; e < 4; e++) acc[t][u][e] = 0.0f;

    gemm_mainloop(Ah, Bh, K, cx, acc);

    const size_t cbase = (size_t)z * sC;
#pragma unroll
    for (int t = 0; t < 4; t++) {
        const int gm = cx.m0 + cx.wm0 + t * 16 + (cx.lane >> 2);
        float rs0 = 0.0f, rs1 = 0.0f;
        float rv0 = 1.0f, rv1 = 1.0f;
        if (OUT_MODE == 6) {
            rv0 = rowscale[(size_t)z * M + gm];
            rv1 = rowscale[(size_t)z * M + gm + 8];
        }
#pragma unroll
        for (int u = 0; u < 8; u++) {
            const int gn = cx.n0 + cx.wn0 + u * 8 + (cx.lane & 3) * 2;
            float v00 = acc[t][u][0], v01 = acc[t][u][1];
            float v10 = acc[t][u][2], v11 = acc[t][u][3];
            if (OUT_MODE == 2) {
                float b0 = bias[gn], b1 = bias[gn + 1];
                v00 += b0; v01 += b1; v10 += b0; v11 += b1;
            }
            if (OUT_MODE == 3) {
                v00 = __expf(v00 * 0.03125f);
                v01 = __expf(v01 * 0.03125f);
                v10 = __expf(v10 * 0.03125f);
                v11 = __expf(v11 * 0.03125f);
                rs0 += v00 + v01;
                rs1 += v10 + v11;
            }
            if (OUT_MODE == 6) {
                v00 *= rv0; v01 *= rv0; v10 *= rv1; v11 *= rv1;
            }
            if (OUT_MODE == 2) {
                *(float2*)(outF + cbase + (size_t)gm * N + gn) = make_float2(v00, v01);
                *(float2*)(outF + cbase + (size_t)(gm + 8) * N + gn) = make_float2(v10, v11);
            } else {
                __half2 hp0; hp0.x = __float2half_rn(v00); hp0.y = __float2half_rn(v01);
                __half2 hp1; hp1.x = __float2half_rn(v10); hp1.y = __float2half_rn(v11);
                *(__half2*)(outHi + cbase + (size_t)gm * N + gn) = hp0;
                *(__half2*)(outHi + cbase + (size_t)(gm + 8) * N + gn) = hp1;
            }
        }
        if (OUT_MODE == 3) {
            rs0 += __shfl_xor_sync(0xffffffffu, rs0, 1);
            rs0 += __shfl_xor_sync(0xffffffffu, rs0, 2);
            rs1 += __shfl_xor_sync(0xffffffffu, rs1, 1);
            rs1 += __shfl_xor_sync(0xffffffffu, rs1, 2);
            if ((cx.lane & 3) == 0) {
                part[cx.wm0 + t * 16 + (cx.lane >> 2)][cx.warp >> 1] = rs0;
                part[cx.wm0 + t * 16 + (cx.lane >> 2) + 8][cx.warp >> 1] = rs1;
            }
        }
    }
    if (OUT_MODE == 3) {
        __syncthreads();
        if (cx.tid < 128) {
            float s = part[cx.tid][0] + part[cx.tid][1] + part[cx.tid][2] + part[cx.tid][3];
            spart[((size_t)z * M + cx.m0 + cx.tid) * 16 + blockIdx.x] = s;
        }
    }
}

// ---------------- host ----------------
extern "C" void kernel_launch(void* const* d_in, const int* in_sizes, int n_in,
                              void* d_out, int out_size)
{
    const float* x  = (const float*)d_in[0];
    const float* y  = (const float*)d_in[1];
    const float* Wq = (const float*)d_in[2];
    const float* Wk = (const float*)d_in[3];
    const float* Wv = (const float*)d_in[4];
    const float* Wo = (const float*)d_in[5];
    const float* bo = (const float*)d_in[6];
    float* out = (float*)d_out;

#define GET(sym, var) void* var; cudaGetSymbolAddress(&var, sym)
    GET(g_xh, xh); GET(g_yh, yh);
    GET(g_wqh, wqh); GET(g_wkh, wkh); GET(g_wvh, wvh); GET(g_woh, woh);
    GET(g_qh, qh); GET(g_kh, kh); GET(g_vh, vh); GET(g_vth, vth);
    GET(g_ph, ph); GET(g_ch, ch);
    GET(g_spart, spart); GET(g_rinv, rinv);
#undef GET

    cudaFuncSetAttribute((void*)gemm_proj, cudaFuncAttributeMaxDynamicSharedMemorySize, SMEM_B);
    cudaFuncSetAttribute((void*)gemm1<2>, cudaFuncAttributeMaxDynamicSharedMemorySize, SMEM_B);
    cudaFuncSetAttribute((void*)gemm1<3>, cudaFuncAttributeMaxDynamicSharedMemorySize, SMEM_B);
    cudaFuncSetAttribute((void*)gemm1<6>, cudaFuncAttributeMaxDynamicSharedMemorySize, SMEM_B);

    const int MBN = BATCH * NSEQ;            // 16384

    // f32 -> f16 conversions (batched)
    {
        int n4 = BATCH * NSEQ * DDIM / 4;
        dim3 g1(n4 / 256, 1, 2);
        conv_xy<<<g1, 256>>>((const float4*)x, (f16*)xh,
                             (const float4*)y, (f16*)yh, n4);
        int w4 = EDIM * DDIM / 4;
        dim3 g2(w4 / 256, 1, 4);
        conv_w<<<g2, 256>>>((const float4*)Wq, (f16*)wqh,
                            (const float4*)Wk, (f16*)wkh,
                            (const float4*)Wv, (f16*)wvh,
                            (const float4*)Wo, (f16*)woh, w4);
    }

    // fused projections: z=0 q=y@Wq^T, z=1 k=x@Wk^T, z=2 v=x@Wv^T
    {
        dim3 grid(EDIM / 256, MBN / 128, 3);
        gemm_proj<<<grid, 256, SMEM_B>>>((f16*)xh, (f16*)yh,
                                         (f16*)wqh, (f16*)wkh, (f16*)wvh,
                                         (f16*)qh, (f16*)kh, (f16*)vh,
                                         MBN, EDIM, DDIM);
    }

    // scores+exp: E = exp(q@k^T / 32), hi out + row partials (grid.x = 16)
    {
        dim3 grid(NSEQ / 256, NSEQ / 128, BATCH);
        gemm1<3><<<grid, 256, SMEM_B>>>((f16*)qh, (f16*)kh, nullptr, (f16*)ph,
                                        nullptr, (float*)spart, nullptr,
                                        NSEQ, NSEQ, EDIM,
                                        (long long)NSEQ * EDIM, (long long)NSEQ * EDIM,
                                        (long long)NSEQ * NSEQ);
    }

    // rinv = 1/rowsum
    rowsum_inv<<<MBN / 256, 256>>>((const float*)spart, (float*)rinv, MBN);

    // transpose V
    {
        dim3 grid(EDIM / 64, NSEQ / 64, BATCH);
        transpose_k<<<grid, 256>>>((f16*)vh, (f16*)vth);
    }

    // ctx = rinv ⊙ (E @ V), hi-only out
    {
        dim3 grid(EDIM / 256, NSEQ / 128, BATCH);
        gemm1<6><<<grid, 256, SMEM_B>>>((f16*)ph, (f16*)vth, nullptr, (f16*)ch,
                                        nullptr, nullptr, (const float*)rinv,
                                        NSEQ, EDIM, NSEQ,
                                        (long long)NSEQ * NSEQ, (long long)EDIM * NSEQ,
                                        (long long)NSEQ * EDIM);
    }

    // out = ctx @ Wo^T + bo (fp32 out)
    {
        dim3 grid(DDIM / 256, MBN / 128, 1);
        gemm1<2><<<grid, 256, SMEM_B>>>((f16*)ch, (f16*)woh, out, nullptr,
                                        bo, nullptr, nullptr, MBN, DDIM, EDIM, 0, 0, 0);
    }

    (void)in_sizes; (void)n_in; (void)out_size;
}